// round 1
// baseline (speedup 1.0000x reference)
#include <cuda_runtime.h>
#include <math.h>

#define S_LEN  2048
#define HID    2048
#define NHEADS 16
#define HS     128
#define QKV_N  (NHEADS * 384)      // 6144
#define INV_NORM 0.08838834764831845f

// ---------------- scratch (device globals; no allocations allowed) ----------
__device__ float g_Q[(size_t)NHEADS * S_LEN * HS];   // [h][s][d]
__device__ float g_K[(size_t)NHEADS * S_LEN * HS];
__device__ float g_V[(size_t)NHEADS * S_LEN * HS];
__device__ float g_attn[(size_t)S_LEN * HID];        // [s][h*128+d]

// packed dual-FMA (Blackwell f32x2): d = a*b + d, two fp32 lanes, bit-exact fp32 rn
__device__ __forceinline__ void fma2(float2& d, const float2& a, const float2& b) {
    asm volatile("fma.rn.f32x2 %0, %1, %2, %0;"
        : "+l"(reinterpret_cast<unsigned long long&>(d))
        : "l"(reinterpret_cast<const unsigned long long&>(a)),
          "l"(reinterpret_cast<const unsigned long long&>(b)));
}

// ---------------------------------------------------------------------------
// Tiled SGEMM: C[M,N] = A[M,K] * B[K,N] + bias[N]
// mode==1: store直 into Cd.  mode==0: scatter into g_Q/g_K/g_V (QKV epilogue).
// BM=BN=128, BK=16, 256 threads, 8x8 microtile (as float2 pairs).
// ---------------------------------------------------------------------------
__global__ __launch_bounds__(256) void gemm128(
    const float* __restrict__ A, const float* __restrict__ B,
    const float* __restrict__ bias, int N, int K,
    float* __restrict__ Cd, int mode)
{
    __shared__ float As[16][132];   // transposed A tile, padded (2-way store conflicts max)
    __shared__ float Bs[16][128];

    const int tid = threadIdx.x;
    const int tx = tid & 15, ty = tid >> 4;
    const int m0 = blockIdx.y * 128, n0 = blockIdx.x * 128;

    float2 acc[8][4];
#pragma unroll
    for (int i = 0; i < 8; i++)
#pragma unroll
        for (int j = 0; j < 4; j++) acc[i][j] = make_float2(0.f, 0.f);

    for (int k0 = 0; k0 < K; k0 += 16) {
#pragma unroll
        for (int i = 0; i < 2; i++) {
            int g  = tid + i * 256;
            int ar = g >> 2, ak = (g & 3) << 2;
            float4 av = *reinterpret_cast<const float4*>(A + (size_t)(m0 + ar) * K + k0 + ak);
            As[ak + 0][ar] = av.x; As[ak + 1][ar] = av.y;
            As[ak + 2][ar] = av.z; As[ak + 3][ar] = av.w;
            int bk = g >> 5, bn = (g & 31) << 2;
            *reinterpret_cast<float4*>(&Bs[bk][bn]) =
                *reinterpret_cast<const float4*>(B + (size_t)(k0 + bk) * N + n0 + bn);
        }
        __syncthreads();
#pragma unroll
        for (int kk = 0; kk < 16; kk++) {
            float4 a0 = *reinterpret_cast<const float4*>(&As[kk][ty * 8]);
            float4 a1 = *reinterpret_cast<const float4*>(&As[kk][ty * 8 + 4]);
            float a[8] = {a0.x, a0.y, a0.z, a0.w, a1.x, a1.y, a1.z, a1.w};
            float4 bA = *reinterpret_cast<const float4*>(&Bs[kk][tx * 4]);
            float4 bB = *reinterpret_cast<const float4*>(&Bs[kk][64 + tx * 4]);
            float2 b[4] = {{bA.x, bA.y}, {bA.z, bA.w}, {bB.x, bB.y}, {bB.z, bB.w}};
#pragma unroll
            for (int i = 0; i < 8; i++) {
                float2 ap = make_float2(a[i], a[i]);
#pragma unroll
                for (int j = 0; j < 4; j++) fma2(acc[i][j], ap, b[j]);
            }
        }
        __syncthreads();
    }

#pragma unroll
    for (int i = 0; i < 8; i++) {
        int m = m0 + ty * 8 + i;
#pragma unroll
        for (int j = 0; j < 4; j++) {
            int ncol = n0 + ((j < 2) ? (tx * 4 + j * 2) : (64 + tx * 4 + (j - 2) * 2));
            float2 v = acc[i][j];
            v.x += bias[ncol];
            v.y += bias[ncol + 1];
            if (mode) {
                *reinterpret_cast<float2*>(Cd + (size_t)m * N + ncol) = v;
            } else {
#pragma unroll
                for (int l = 0; l < 2; l++) {
                    int n = ncol + l;
                    float val = l ? v.y : v.x;
                    int h = n / 384, e = n - h * 384;
                    size_t idx = ((size_t)h * S_LEN + m) * HS;
                    if (e < HS)          g_Q[idx + e] = val;
                    else if (e < 2 * HS) g_K[idx + e - HS] = val;
                    else                 g_V[idx + e - 2 * HS] = val;
                }
            }
        }
    }
}

// ---------------------------------------------------------------------------
// Rotary: first 32 dims of Q and K, per (s, h). 256 thr = 16 heads x 16 pairs.
// ---------------------------------------------------------------------------
__global__ __launch_bounds__(256) void rotary_kernel()
{
    int s = blockIdx.x;
    int h = threadIdx.x >> 4;
    int j = threadIdx.x & 15;
    // inv_freq = 10000^(-j/16); double then round, matches f32 pow within ~1 ulp
    float inv  = (float)exp(-(double)j * (9.210340371976184 / 16.0));
    float freq = (float)s * inv;
    float sn, c;
    sincosf(freq, &sn, &c);
    size_t base = ((size_t)h * S_LEN + s) * HS;
    {
        float x0 = g_Q[base + j], x1 = g_Q[base + j + 16];
        g_Q[base + j]      = x0 * c - x1 * sn;
        g_Q[base + j + 16] = x1 * c + x0 * sn;
    }
    {
        float x0 = g_K[base + j], x1 = g_K[base + j + 16];
        g_K[base + j]      = x0 * c - x1 * sn;
        g_K[base + j + 16] = x1 * c + x0 * sn;
    }
}

// ---------------------------------------------------------------------------
// Causal flash attention, fp32. Block = (head, q-tile of 64). 256 threads.
// Q/K tiles stored transposed [d][m] with XOR swizzle -> conflict-free LDS.128.
// Thread (ty,tx): S rows 4ty..+3, cols 4tx..+3; O rows 4ty..+3, d-slices
// tx*4..+3 and 64+tx*4..+3.
// ---------------------------------------------------------------------------
__global__ __launch_bounds__(256) void flash_kernel()
{
    const int h  = blockIdx.y;
    const int qt = (gridDim.x - 1) - blockIdx.x;   // heavy tiles launch first
    const int q0 = qt * 64;
    const float* Qh = g_Q + (size_t)h * S_LEN * HS;
    const float* Kh = g_K + (size_t)h * S_LEN * HS;
    const float* Vh = g_V + (size_t)h * S_LEN * HS;

    extern __shared__ float sm[];
    float* sQt = sm;             // 128 x 64  (transposed, swizzled)
    float* sKt = sm + 8192;      // 128 x 64
    float* sV  = sm + 16384;     // 64 x 128 (row major)
    float* sP  = sm + 24576;     // 64 x 64

    const int tid = threadIdx.x;
    const int tx = tid & 15, ty = tid >> 4;

    // load Q tile, transposed + swizzled
#pragma unroll
    for (int i = 0; i < 8; i++) {
        int g = tid + i * 256;
        int n = g >> 5, dq = (g & 31) << 2;
        float4 v = *reinterpret_cast<const float4*>(Qh + (size_t)(q0 + n) * HS + dq);
        float vv[4] = {v.x, v.y, v.z, v.w};
#pragma unroll
        for (int l = 0; l < 4; l++) {
            int d = dq + l;
            sQt[d * 64 + ((((n >> 2) ^ (d & 15)) << 2) | (n & 3))] = vv[l];
        }
    }

    float2 o[4][4];
#pragma unroll
    for (int i = 0; i < 4; i++)
#pragma unroll
        for (int j = 0; j < 4; j++) o[i][j] = make_float2(0.f, 0.f);
    float mi[4], li[4];
#pragma unroll
    for (int i = 0; i < 4; i++) { mi[i] = -3.0e38f; li[i] = 0.f; }

    for (int kt = 0; kt <= qt; kt++) {
        __syncthreads();          // prev PV done before overwriting sKt/sV/sP
        const int kb0 = kt * 64;
#pragma unroll
        for (int i = 0; i < 8; i++) {
            int g = tid + i * 256;
            int n = g >> 5, dq = (g & 31) << 2;
            float4 kv = *reinterpret_cast<const float4*>(Kh + (size_t)(kb0 + n) * HS + dq);
            float kk4[4] = {kv.x, kv.y, kv.z, kv.w};
#pragma unroll
            for (int l = 0; l < 4; l++) {
                int d = dq + l;
                sKt[d * 64 + ((((n >> 2) ^ (d & 15)) << 2) | (n & 3))] = kk4[l];
            }
            *reinterpret_cast<float4*>(&sV[n * HS + dq]) =
                *reinterpret_cast<const float4*>(Vh + (size_t)(kb0 + n) * HS + dq);
        }
        __syncthreads();

        // ---- S = Q K^T (per-thread 4x4), via transposed smem ----
        float2 s2[4][2];
#pragma unroll
        for (int i = 0; i < 4; i++) { s2[i][0] = make_float2(0.f, 0.f); s2[i][1] = make_float2(0.f, 0.f); }
#pragma unroll 8
        for (int d = 0; d < 128; d++) {
            float4 qa  = *reinterpret_cast<const float4*>(&sQt[d * 64 + ((ty ^ (d & 15)) << 2)]);
            float4 kbv = *reinterpret_cast<const float4*>(&sKt[d * 64 + ((tx ^ (d & 15)) << 2)]);
            float2 k0v = make_float2(kbv.x, kbv.y), k1v = make_float2(kbv.z, kbv.w);
            float qv[4] = {qa.x, qa.y, qa.z, qa.w};
#pragma unroll
            for (int i = 0; i < 4; i++) {
                float2 ap = make_float2(qv[i], qv[i]);
                fma2(s2[i][0], ap, k0v);
                fma2(s2[i][1], ap, k1v);
            }
        }
        float sv[4][4];
#pragma unroll
        for (int i = 0; i < 4; i++) {
            sv[i][0] = s2[i][0].x * INV_NORM; sv[i][1] = s2[i][0].y * INV_NORM;
            sv[i][2] = s2[i][1].x * INV_NORM; sv[i][3] = s2[i][1].y * INV_NORM;
        }
        if (kt == qt) {           // diagonal tile: causal mask
#pragma unroll
            for (int i = 0; i < 4; i++) {
                int q = q0 + ty * 4 + i;
#pragma unroll
                for (int j = 0; j < 4; j++) {
                    int k = kb0 + tx * 4 + j;
                    if (k > q) sv[i][j] = -1.0e30f;
                }
            }
        }

        // ---- online softmax (row stats reduced over the 16 tx lanes) ----
#pragma unroll
        for (int i = 0; i < 4; i++) {
            float rm = fmaxf(fmaxf(sv[i][0], sv[i][1]), fmaxf(sv[i][2], sv[i][3]));
#pragma unroll
            for (int off = 8; off; off >>= 1)
                rm = fmaxf(rm, __shfl_xor_sync(0xffffffffu, rm, off));
            float mn = fmaxf(mi[i], rm);
            float alpha = expf(mi[i] - mn);
            mi[i] = mn;
            float ps[4]; float rs = 0.f;
#pragma unroll
            for (int j = 0; j < 4; j++) { ps[j] = expf(sv[i][j] - mn); rs += ps[j]; }
#pragma unroll
            for (int off = 8; off; off >>= 1)
                rs += __shfl_xor_sync(0xffffffffu, rs, off);
            li[i] = li[i] * alpha + rs;
#pragma unroll
            for (int j = 0; j < 4; j++) { o[i][j].x *= alpha; o[i][j].y *= alpha; }
            *reinterpret_cast<float4*>(&sP[(ty * 4 + i) * 64 + tx * 4]) =
                make_float4(ps[0], ps[1], ps[2], ps[3]);
        }
        __syncthreads();

        // ---- O += P V ----
#pragma unroll 4
        for (int k = 0; k < 64; k++) {
            float4 v0 = *reinterpret_cast<const float4*>(&sV[k * HS + tx * 4]);
            float4 v1 = *reinterpret_cast<const float4*>(&sV[k * HS + 64 + tx * 4]);
            float2 v00 = make_float2(v0.x, v0.y), v01 = make_float2(v0.z, v0.w);
            float2 v10 = make_float2(v1.x, v1.y), v11 = make_float2(v1.z, v1.w);
#pragma unroll
            for (int i = 0; i < 4; i++) {
                float p = sP[(ty * 4 + i) * 64 + k];
                float2 pp = make_float2(p, p);
                fma2(o[i][0], pp, v00); fma2(o[i][1], pp, v01);
                fma2(o[i][2], pp, v10); fma2(o[i][3], pp, v11);
            }
        }
    }

    // ---- normalize + write attn [s][h*128+d] ----
#pragma unroll
    for (int i = 0; i < 4; i++) {
        float invl = 1.0f / li[i];
        int row = q0 + ty * 4 + i;
        float4 w0 = make_float4(o[i][0].x * invl, o[i][0].y * invl,
                                o[i][1].x * invl, o[i][1].y * invl);
        float4 w1 = make_float4(o[i][2].x * invl, o[i][2].y * invl,
                                o[i][3].x * invl, o[i][3].y * invl);
        float* dst = g_attn + (size_t)row * HID + h * HS;
        *reinterpret_cast<float4*>(dst + tx * 4)      = w0;
        *reinterpret_cast<float4*>(dst + 64 + tx * 4) = w1;
    }
}

// ---------------------------------------------------------------------------
extern "C" void kernel_launch(void* const* d_in, const int* in_sizes, int n_in,
                              void* d_out, int out_size)
{
    (void)in_sizes; (void)n_in; (void)out_size;
    const float* hidden = (const float*)d_in[0];
    // d_in[1] = attention_mask (tril) — causal mask applied analytically
    const float* qkvk = (const float*)d_in[2];
    const float* qkvb = (const float*)d_in[3];
    const float* outk = (const float*)d_in[4];
    const float* outb = (const float*)d_in[5];
    float* out = (float*)d_out;

    cudaFuncSetAttribute(flash_kernel,
                         cudaFuncAttributeMaxDynamicSharedMemorySize, 114688);

    void* attnp = nullptr;
    cudaGetSymbolAddress(&attnp, g_attn);

    // 1) QKV projection + bias, scatter to per-head Q/K/V
    gemm128<<<dim3(QKV_N / 128, S_LEN / 128), 256>>>(
        hidden, qkvk, qkvb, QKV_N, HID, nullptr, 0);

    // 2) rotary on Q,K (first 32 dims)
    rotary_kernel<<<S_LEN, 256>>>();

    // 3) causal flash attention
    flash_kernel<<<dim3(S_LEN / 64, NHEADS), 256, 114688>>>();

    // 4) output projection + bias
    gemm128<<<dim3(HID / 128, S_LEN / 128), 256>>>(
        (const float*)attnp, outk, outb, HID, HID, out, 1);
}

// round 3
// speedup vs baseline: 1.4026x; 1.4026x over previous
#include <cuda_runtime.h>
#include <cuda_bf16.h>
#include <math.h>
#include <stdint.h>

#define S_LEN  2048
#define HID    2048
#define NHEADS 16
#define HS     128
#define QKV_N  6144
#define KTOT   2048
#define INV_NORM 0.08838834764831845f

// ---------------- scratch (device globals; no allocations allowed) ----------
__device__ float g_Q[(size_t)NHEADS * S_LEN * HS];   // [h][s][d] fp32
__device__ float g_K[(size_t)NHEADS * S_LEN * HS];
__device__ float g_V[(size_t)NHEADS * S_LEN * HS];
__device__ __nv_bfloat16 g_Ah[(size_t)S_LEN * HID];     // hidden hi [m][k]
__device__ __nv_bfloat16 g_Al[(size_t)S_LEN * HID];
__device__ __nv_bfloat16 g_Bqh[(size_t)QKV_N * HID];    // qkv kernel^T hi [n][k]
__device__ __nv_bfloat16 g_Bql[(size_t)QKV_N * HID];
__device__ __nv_bfloat16 g_Boh[(size_t)HID * HID];      // out kernel^T hi [n][k]
__device__ __nv_bfloat16 g_Bol[(size_t)HID * HID];
__device__ __nv_bfloat16 g_ATh[(size_t)S_LEN * HID];    // attn out hi [m][k]
__device__ __nv_bfloat16 g_ATl[(size_t)S_LEN * HID];

// ------------------------------- helpers ------------------------------------
__device__ __forceinline__ uint32_t smem_to_u32(const void* p) {
    uint32_t a;
    asm("{ .reg .u64 t; cvta.to.shared.u64 t, %1; cvt.u32.u64 %0, t; }"
        : "=r"(a) : "l"(p));
    return a;
}
__device__ __forceinline__ void cp_async16(uint32_t dst, const void* src) {
    asm volatile("cp.async.cg.shared.global [%0], [%1], 16;"
                 :: "r"(dst), "l"(src) : "memory");
}
#define CP_COMMIT() asm volatile("cp.async.commit_group;" ::: "memory")
#define CP_WAIT(n)  asm volatile("cp.async.wait_group %0;" :: "n"(n) : "memory")

// bf16 mma, fp32 accumulate (baseline PTX, HMMA path)
__device__ __forceinline__ void mma_bf16(float* c, const uint32_t* a, const uint32_t* b) {
    asm volatile(
        "mma.sync.aligned.m16n8k16.row.col.f32.bf16.bf16.f32 "
        "{%0,%1,%2,%3}, {%4,%5,%6,%7}, {%8,%9}, {%0,%1,%2,%3};"
        : "+f"(c[0]), "+f"(c[1]), "+f"(c[2]), "+f"(c[3])
        : "r"(a[0]), "r"(a[1]), "r"(a[2]), "r"(a[3]), "r"(b[0]), "r"(b[1]));
}

// packed dual-FMA (f32x2) for the flash kernel
__device__ __forceinline__ void fma2(float2& d, const float2& a, const float2& b) {
    asm volatile("fma.rn.f32x2 %0, %1, %2, %0;"
        : "+l"(reinterpret_cast<unsigned long long&>(d))
        : "l"(reinterpret_cast<const unsigned long long&>(a)),
          "l"(reinterpret_cast<const unsigned long long&>(b)));
}

// ---------------------------------------------------------------------------
// Conversion kernels: fp32 -> bf16 hi/lo split (and transposed variant for B)
// ---------------------------------------------------------------------------
__global__ __launch_bounds__(256) void conv_split(
    const float4* __restrict__ X, __nv_bfloat162* __restrict__ H,
    __nv_bfloat162* __restrict__ L)
{
    int i = blockIdx.x * 256 + threadIdx.x;
    float4 v = X[i];
    __nv_bfloat16 h0 = __float2bfloat16_rn(v.x), h1 = __float2bfloat16_rn(v.y);
    __nv_bfloat16 h2 = __float2bfloat16_rn(v.z), h3 = __float2bfloat16_rn(v.w);
    __nv_bfloat16 l0 = __float2bfloat16_rn(v.x - __bfloat162float(h0));
    __nv_bfloat16 l1 = __float2bfloat16_rn(v.y - __bfloat162float(h1));
    __nv_bfloat16 l2 = __float2bfloat16_rn(v.z - __bfloat162float(h2));
    __nv_bfloat16 l3 = __float2bfloat16_rn(v.w - __bfloat162float(h3));
    H[2 * i] = __halves2bfloat162(h0, h1); H[2 * i + 1] = __halves2bfloat162(h2, h3);
    L[2 * i] = __halves2bfloat162(l0, l1); L[2 * i + 1] = __halves2bfloat162(l2, l3);
}

__global__ __launch_bounds__(256) void conv_transpose_split(
    const float* __restrict__ B, __nv_bfloat16* __restrict__ H,
    __nv_bfloat16* __restrict__ L, int K, int N)
{
    __shared__ float t[32][33];
    int x = threadIdx.x & 31, y = threadIdx.x >> 5;
    int n0 = blockIdx.x * 32, k0 = blockIdx.y * 32;
#pragma unroll
    for (int j = 0; j < 32; j += 8)
        t[y + j][x] = B[(size_t)(k0 + y + j) * N + n0 + x];
    __syncthreads();
#pragma unroll
    for (int j = 0; j < 32; j += 8) {
        float v = t[x][y + j];
        __nv_bfloat16 h = __float2bfloat16_rn(v);
        __nv_bfloat16 l = __float2bfloat16_rn(v - __bfloat162float(h));
        size_t o = (size_t)(n0 + y + j) * K + k0 + x;
        H[o] = h; L[o] = l;
    }
}

// ---------------------------------------------------------------------------
// bf16x3 mma.sync GEMM: C[M,N] = A*B^T + bias
// A=[M,K] K-major hi/lo, B=[N,K] K-major hi/lo.
// BM=BN=128, BK=32. 256 thr = 8 warps (2 m x 4 n), warp tile 64x32.
// smem row stride = 40 halves (80B): conflict-free b32 fragment loads.
// mode 1: fp32 store into Cout.  mode 0: QKV scatter into g_Q/g_K/g_V.
// ---------------------------------------------------------------------------
#define GBK 32
#define GNITER (KTOT / GBK)
#define ROWSTR 40                 // halves
#define BUFH (128 * ROWSTR)       // 5120 halves per operand buffer
#define STGH (4 * BUFH)           // halves per stage
#define GEMM_SMEM (2 * STGH * 2)  // bytes = 81920

__global__ __launch_bounds__(256, 1) void gemm_mma(
    const __nv_bfloat16* __restrict__ Ah, const __nv_bfloat16* __restrict__ Al,
    const __nv_bfloat16* __restrict__ Bh, const __nv_bfloat16* __restrict__ Bl,
    const float* __restrict__ bias, int N, float* __restrict__ Cout, int mode)
{
    extern __shared__ __align__(16) __nv_bfloat16 sm[];
    const int tid = threadIdx.x;
    const int wid = tid >> 5, lane = tid & 31;
    const int wm = wid >> 2, wn = wid & 3;          // 2 x 4 warp grid
    const int n0 = blockIdx.x * 128, m0 = blockIdx.y * 128;
    const uint32_t sbase = smem_to_u32(sm);

    const int r  = lane >> 2;          // 0..7
    const int c2 = (lane & 3) * 2;     // 0,2,4,6

    float acc[4][4][4];
#pragma unroll
    for (int i = 0; i < 4; i++)
#pragma unroll
        for (int j = 0; j < 4; j++)
#pragma unroll
            for (int q = 0; q < 4; q++) acc[i][j][q] = 0.f;

    // ---- async stage loader ----
    auto load_stage = [&](int s, int k0) {
        const uint32_t st = sbase + (uint32_t)s * STGH * 2;
#pragma unroll
        for (int i = 0; i < 2; i++) {
            int c = tid + i * 256;           // 0..511
            int row = c >> 2, kc = c & 3;
            uint32_t doff = (uint32_t)(row * ROWSTR + kc * 8) * 2;  // bytes
            size_t goA = (size_t)(m0 + row) * KTOT + k0 + kc * 8;
            size_t goB = (size_t)(n0 + row) * KTOT + k0 + kc * 8;
            cp_async16(st + doff,                Ah + goA);
            cp_async16(st + BUFH * 2 + doff,     Al + goA);
            cp_async16(st + 2 * BUFH * 2 + doff, Bh + goB);
            cp_async16(st + 3 * BUFH * 2 + doff, Bl + goB);
        }
    };

    load_stage(0, 0);
    CP_COMMIT();

    for (int it = 0; it < GNITER; it++) {
        const int s = it & 1;
        if (it + 1 < GNITER) {
            load_stage(s ^ 1, (it + 1) * GBK);
            CP_COMMIT();
            CP_WAIT(1);
        } else {
            CP_WAIT(0);
        }
        __syncthreads();

        const __nv_bfloat16* pAh = sm + s * STGH;
        const __nv_bfloat16* pAl = pAh + BUFH;
        const __nv_bfloat16* pBh = pAh + 2 * BUFH;
        const __nv_bfloat16* pBl = pAh + 3 * BUFH;

#pragma unroll
        for (int ks = 0; ks < 2; ks++) {
            uint32_t ah[4][4], al[4][4], bh[4][2], bl[4][2];
#pragma unroll
            for (int i = 0; i < 4; i++) {
                int ro = (wm * 64 + i * 16 + r) * ROWSTR + ks * 16 + c2;
                ah[i][0] = *reinterpret_cast<const uint32_t*>(pAh + ro);
                ah[i][1] = *reinterpret_cast<const uint32_t*>(pAh + ro + 8 * ROWSTR);
                ah[i][2] = *reinterpret_cast<const uint32_t*>(pAh + ro + 8);
                ah[i][3] = *reinterpret_cast<const uint32_t*>(pAh + ro + 8 * ROWSTR + 8);
                al[i][0] = *reinterpret_cast<const uint32_t*>(pAl + ro);
                al[i][1] = *reinterpret_cast<const uint32_t*>(pAl + ro + 8 * ROWSTR);
                al[i][2] = *reinterpret_cast<const uint32_t*>(pAl + ro + 8);
                al[i][3] = *reinterpret_cast<const uint32_t*>(pAl + ro + 8 * ROWSTR + 8);
            }
#pragma unroll
            for (int j = 0; j < 4; j++) {
                int ro = (wn * 32 + j * 8 + r) * ROWSTR + ks * 16 + c2;
                bh[j][0] = *reinterpret_cast<const uint32_t*>(pBh + ro);
                bh[j][1] = *reinterpret_cast<const uint32_t*>(pBh + ro + 8);
                bl[j][0] = *reinterpret_cast<const uint32_t*>(pBl + ro);
                bl[j][1] = *reinterpret_cast<const uint32_t*>(pBl + ro + 8);
            }
#pragma unroll
            for (int i = 0; i < 4; i++)
#pragma unroll
                for (int j = 0; j < 4; j++) {
                    mma_bf16(acc[i][j], ah[i], bh[j]);
                    mma_bf16(acc[i][j], ah[i], bl[j]);
                    mma_bf16(acc[i][j], al[i], bh[j]);
                }
        }
        __syncthreads();
    }

    // ---- epilogue: registers -> global (+bias), optional QKV scatter ----
#pragma unroll
    for (int i = 0; i < 4; i++) {
#pragma unroll
        for (int j = 0; j < 4; j++) {
            int n = n0 + wn * 32 + j * 8 + c2;
            float2 bv = *reinterpret_cast<const float2*>(bias + n);
#pragma unroll
            for (int half = 0; half < 2; half++) {
                int m = m0 + wm * 64 + i * 16 + r + half * 8;
                float2 v = make_float2(acc[i][j][half * 2] + bv.x,
                                       acc[i][j][half * 2 + 1] + bv.y);
                if (mode) {
                    *reinterpret_cast<float2*>(Cout + (size_t)m * N + n) = v;
                } else {
                    int h = n / 384, e = n - h * 384;
                    int seg = e >> 7, d = e & 127;
                    float* base = (seg == 0) ? g_Q : (seg == 1) ? g_K : g_V;
                    *reinterpret_cast<float2*>(base + ((size_t)h * S_LEN + m) * HS + d) = v;
                }
            }
        }
    }
}

// ---------------------------------------------------------------------------
// Rotary: first 32 dims of Q and K, per (s, h).
// ---------------------------------------------------------------------------
__global__ __launch_bounds__(256) void rotary_kernel()
{
    int s = blockIdx.x;
    int h = threadIdx.x >> 4;
    int j = threadIdx.x & 15;
    float inv  = (float)exp(-(double)j * (9.210340371976184 / 16.0));
    float freq = (float)s * inv;
    float sn, c;
    sincosf(freq, &sn, &c);
    size_t base = ((size_t)h * S_LEN + s) * HS;
    {
        float x0 = g_Q[base + j], x1 = g_Q[base + j + 16];
        g_Q[base + j]      = x0 * c - x1 * sn;
        g_Q[base + j + 16] = x1 * c + x0 * sn;
    }
    {
        float x0 = g_K[base + j], x1 = g_K[base + j + 16];
        g_K[base + j]      = x0 * c - x1 * sn;
        g_K[base + j + 16] = x1 * c + x0 * sn;
    }
}

// ---------------------------------------------------------------------------
// Causal flash attention (fp32 SIMT), writes output as bf16 hi/lo split.
// ---------------------------------------------------------------------------
__device__ __forceinline__ void store_hl4(__nv_bfloat16* Hp, __nv_bfloat16* Lp,
                                          float a, float b, float c, float d)
{
    __nv_bfloat16 ha = __float2bfloat16_rn(a), hb = __float2bfloat16_rn(b);
    __nv_bfloat16 hc = __float2bfloat16_rn(c), hd = __float2bfloat16_rn(d);
    __nv_bfloat16 la = __float2bfloat16_rn(a - __bfloat162float(ha));
    __nv_bfloat16 lb = __float2bfloat16_rn(b - __bfloat162float(hb));
    __nv_bfloat16 lc = __float2bfloat16_rn(c - __bfloat162float(hc));
    __nv_bfloat16 ld = __float2bfloat16_rn(d - __bfloat162float(hd));
    reinterpret_cast<__nv_bfloat162*>(Hp)[0] = __halves2bfloat162(ha, hb);
    reinterpret_cast<__nv_bfloat162*>(Hp)[1] = __halves2bfloat162(hc, hd);
    reinterpret_cast<__nv_bfloat162*>(Lp)[0] = __halves2bfloat162(la, lb);
    reinterpret_cast<__nv_bfloat162*>(Lp)[1] = __halves2bfloat162(lc, ld);
}

__global__ __launch_bounds__(256) void flash_kernel()
{
    const int h  = blockIdx.y;
    const int qt = (gridDim.x - 1) - blockIdx.x;
    const int q0 = qt * 64;
    const float* Qh = g_Q + (size_t)h * S_LEN * HS;
    const float* Kh = g_K + (size_t)h * S_LEN * HS;
    const float* Vh = g_V + (size_t)h * S_LEN * HS;

    extern __shared__ float smf[];
    float* sQt = smf;
    float* sKt = smf + 8192;
    float* sV  = smf + 16384;
    float* sP  = smf + 24576;

    const int tid = threadIdx.x;
    const int tx = tid & 15, ty = tid >> 4;

#pragma unroll
    for (int i = 0; i < 8; i++) {
        int g = tid + i * 256;
        int n = g >> 5, dq = (g & 31) << 2;
        float4 v = *reinterpret_cast<const float4*>(Qh + (size_t)(q0 + n) * HS + dq);
        float vv[4] = {v.x, v.y, v.z, v.w};
#pragma unroll
        for (int l = 0; l < 4; l++) {
            int d = dq + l;
            sQt[d * 64 + ((((n >> 2) ^ (d & 15)) << 2) | (n & 3))] = vv[l];
        }
    }

    float2 o[4][4];
#pragma unroll
    for (int i = 0; i < 4; i++)
#pragma unroll
        for (int j = 0; j < 4; j++) o[i][j] = make_float2(0.f, 0.f);
    float mi[4], li[4];
#pragma unroll
    for (int i = 0; i < 4; i++) { mi[i] = -3.0e38f; li[i] = 0.f; }

    for (int kt = 0; kt <= qt; kt++) {
        __syncthreads();
        const int kb0 = kt * 64;
#pragma unroll
        for (int i = 0; i < 8; i++) {
            int g = tid + i * 256;
            int n = g >> 5, dq = (g & 31) << 2;
            float4 kv = *reinterpret_cast<const float4*>(Kh + (size_t)(kb0 + n) * HS + dq);
            float kk4[4] = {kv.x, kv.y, kv.z, kv.w};
#pragma unroll
            for (int l = 0; l < 4; l++) {
                int d = dq + l;
                sKt[d * 64 + ((((n >> 2) ^ (d & 15)) << 2) | (n & 3))] = kk4[l];
            }
            *reinterpret_cast<float4*>(&sV[n * HS + dq]) =
                *reinterpret_cast<const float4*>(Vh + (size_t)(kb0 + n) * HS + dq);
        }
        __syncthreads();

        float2 s2[4][2];
#pragma unroll
        for (int i = 0; i < 4; i++) { s2[i][0] = make_float2(0.f, 0.f); s2[i][1] = make_float2(0.f, 0.f); }
#pragma unroll 8
        for (int d = 0; d < 128; d++) {
            float4 qa  = *reinterpret_cast<const float4*>(&sQt[d * 64 + ((ty ^ (d & 15)) << 2)]);
            float4 kbv = *reinterpret_cast<const float4*>(&sKt[d * 64 + ((tx ^ (d & 15)) << 2)]);
            float2 k0v = make_float2(kbv.x, kbv.y), k1v = make_float2(kbv.z, kbv.w);
            float qv[4] = {qa.x, qa.y, qa.z, qa.w};
#pragma unroll
            for (int i = 0; i < 4; i++) {
                float2 ap = make_float2(qv[i], qv[i]);
                fma2(s2[i][0], ap, k0v);
                fma2(s2[i][1], ap, k1v);
            }
        }
        float sv[4][4];
#pragma unroll
        for (int i = 0; i < 4; i++) {
            sv[i][0] = s2[i][0].x * INV_NORM; sv[i][1] = s2[i][0].y * INV_NORM;
            sv[i][2] = s2[i][1].x * INV_NORM; sv[i][3] = s2[i][1].y * INV_NORM;
        }
        if (kt == qt) {
#pragma unroll
            for (int i = 0; i < 4; i++) {
                int q = q0 + ty * 4 + i;
#pragma unroll
                for (int j = 0; j < 4; j++) {
                    int k = kb0 + tx * 4 + j;
                    if (k > q) sv[i][j] = -1.0e30f;
                }
            }
        }

#pragma unroll
        for (int i = 0; i < 4; i++) {
            float rm = fmaxf(fmaxf(sv[i][0], sv[i][1]), fmaxf(sv[i][2], sv[i][3]));
#pragma unroll
            for (int off = 8; off; off >>= 1)
                rm = fmaxf(rm, __shfl_xor_sync(0xffffffffu, rm, off));
            float mn = fmaxf(mi[i], rm);
            float alpha = expf(mi[i] - mn);
            mi[i] = mn;
            float ps[4]; float rs = 0.f;
#pragma unroll
            for (int j = 0; j < 4; j++) { ps[j] = expf(sv[i][j] - mn); rs += ps[j]; }
#pragma unroll
            for (int off = 8; off; off >>= 1)
                rs += __shfl_xor_sync(0xffffffffu, rs, off);
            li[i] = li[i] * alpha + rs;
#pragma unroll
            for (int j = 0; j < 4; j++) { o[i][j].x *= alpha; o[i][j].y *= alpha; }
            *reinterpret_cast<float4*>(&sP[(ty * 4 + i) * 64 + tx * 4]) =
                make_float4(ps[0], ps[1], ps[2], ps[3]);
        }
        __syncthreads();

#pragma unroll 4
        for (int k = 0; k < 64; k++) {
            float4 v0 = *reinterpret_cast<const float4*>(&sV[k * HS + tx * 4]);
            float4 v1 = *reinterpret_cast<const float4*>(&sV[k * HS + 64 + tx * 4]);
            float2 v00 = make_float2(v0.x, v0.y), v01 = make_float2(v0.z, v0.w);
            float2 v10 = make_float2(v1.x, v1.y), v11 = make_float2(v1.z, v1.w);
#pragma unroll
            for (int i = 0; i < 4; i++) {
                float p = sP[(ty * 4 + i) * 64 + k];
                float2 pp = make_float2(p, p);
                fma2(o[i][0], pp, v00); fma2(o[i][1], pp, v01);
                fma2(o[i][2], pp, v10); fma2(o[i][3], pp, v11);
            }
        }
    }

#pragma unroll
    for (int i = 0; i < 4; i++) {
        float invl = 1.0f / li[i];
        int row = q0 + ty * 4 + i;
        size_t base = (size_t)row * HID + h * HS;
        store_hl4(g_ATh + base + tx * 4, g_ATl + base + tx * 4,
                  o[i][0].x * invl, o[i][0].y * invl, o[i][1].x * invl, o[i][1].y * invl);
        store_hl4(g_ATh + base + 64 + tx * 4, g_ATl + base + 64 + tx * 4,
                  o[i][2].x * invl, o[i][2].y * invl, o[i][3].x * invl, o[i][3].y * invl);
    }
}

// ---------------------------------------------------------------------------
extern "C" void kernel_launch(void* const* d_in, const int* in_sizes, int n_in,
                              void* d_out, int out_size)
{
    (void)in_sizes; (void)n_in; (void)out_size;
    const float* hidden = (const float*)d_in[0];
    const float* qkvk = (const float*)d_in[2];
    const float* qkvb = (const float*)d_in[3];
    const float* outk = (const float*)d_in[4];
    const float* outb = (const float*)d_in[5];
    float* out = (float*)d_out;

    cudaFuncSetAttribute(gemm_mma, cudaFuncAttributeMaxDynamicSharedMemorySize, GEMM_SMEM);
    cudaFuncSetAttribute(flash_kernel, cudaFuncAttributeMaxDynamicSharedMemorySize, 114688);

    void *Ah, *Al, *Bqh, *Bql, *Boh, *Bol, *ATh, *ATl;
    cudaGetSymbolAddress(&Ah, g_Ah);   cudaGetSymbolAddress(&Al, g_Al);
    cudaGetSymbolAddress(&Bqh, g_Bqh); cudaGetSymbolAddress(&Bql, g_Bql);
    cudaGetSymbolAddress(&Boh, g_Boh); cudaGetSymbolAddress(&Bol, g_Bol);
    cudaGetSymbolAddress(&ATh, g_ATh); cudaGetSymbolAddress(&ATl, g_ATl);

    // 0) operand conversion / transpose
    conv_split<<<(S_LEN * HID) / 1024, 256>>>(
        (const float4*)hidden, (__nv_bfloat162*)Ah, (__nv_bfloat162*)Al);
    conv_transpose_split<<<dim3(QKV_N / 32, HID / 32), 256>>>(
        qkvk, (__nv_bfloat16*)Bqh, (__nv_bfloat16*)Bql, HID, QKV_N);
    conv_transpose_split<<<dim3(HID / 32, HID / 32), 256>>>(
        outk, (__nv_bfloat16*)Boh, (__nv_bfloat16*)Bol, HID, HID);

    // 1) QKV projection (mma.sync bf16x3) + bias, scatter to Q/K/V
    gemm_mma<<<dim3(QKV_N / 128, S_LEN / 128), 256, GEMM_SMEM>>>(
        (const __nv_bfloat16*)Ah, (const __nv_bfloat16*)Al,
        (const __nv_bfloat16*)Bqh, (const __nv_bfloat16*)Bql,
        qkvb, QKV_N, nullptr, 0);

    // 2) rotary on Q,K
    rotary_kernel<<<S_LEN, 256>>>();

    // 3) causal flash attention (writes bf16 hi/lo attn)
    flash_kernel<<<dim3(S_LEN / 64, NHEADS), 256, 114688>>>();

    // 4) output projection (mma.sync bf16x3) + bias
    gemm_mma<<<dim3(HID / 128, S_LEN / 128), 256, GEMM_SMEM>>>(
        (const __nv_bfloat16*)ATh, (const __nv_bfloat16*)ATl,
        (const __nv_bfloat16*)Boh, (const __nv_bfloat16*)Bol,
        outb, HID, out, 1);
}

// round 4
// speedup vs baseline: 2.2861x; 1.6299x over previous
#include <cuda_runtime.h>
#include <cuda_bf16.h>
#include <math.h>
#include <stdint.h>

#define S_LEN  2048
#define HID    2048
#define NHEADS 16
#define HS     128
#define QKV_N  6144
#define KTOT   2048
#define INV_NORM 0.08838834764831845f

// ---------------- scratch (device globals; no allocations allowed) ----------
__device__ float g_Q[(size_t)NHEADS * S_LEN * HS];   // [h][s][d] fp32
__device__ float g_K[(size_t)NHEADS * S_LEN * HS];
__device__ float g_V[(size_t)NHEADS * S_LEN * HS];
__device__ __nv_bfloat16 g_Ah[(size_t)S_LEN * HID];     // hidden hi [m][k]
__device__ __nv_bfloat16 g_Al[(size_t)S_LEN * HID];
__device__ __nv_bfloat16 g_Bqh[(size_t)QKV_N * HID];    // qkv kernel^T hi [n][k]
__device__ __nv_bfloat16 g_Bql[(size_t)QKV_N * HID];
__device__ __nv_bfloat16 g_Boh[(size_t)HID * HID];      // out kernel^T hi [n][k]
__device__ __nv_bfloat16 g_Bol[(size_t)HID * HID];
__device__ __nv_bfloat16 g_ATh[(size_t)S_LEN * HID];    // attn out hi [m][k]
__device__ __nv_bfloat16 g_ATl[(size_t)S_LEN * HID];
// flash operands (bf16 hi/lo)
__device__ __nv_bfloat16 g_Qh[(size_t)NHEADS * S_LEN * HS];   // [h][s][d]
__device__ __nv_bfloat16 g_Ql[(size_t)NHEADS * S_LEN * HS];
__device__ __nv_bfloat16 g_Kh[(size_t)NHEADS * S_LEN * HS];
__device__ __nv_bfloat16 g_Kl[(size_t)NHEADS * S_LEN * HS];
__device__ __nv_bfloat16 g_Vth[(size_t)NHEADS * HS * S_LEN];  // V^T [h][d][s]
__device__ __nv_bfloat16 g_Vtl[(size_t)NHEADS * HS * S_LEN];

// ------------------------------- helpers ------------------------------------
__device__ __forceinline__ uint32_t smem_to_u32(const void* p) {
    uint32_t a;
    asm("{ .reg .u64 t; cvta.to.shared.u64 t, %1; cvt.u32.u64 %0, t; }"
        : "=r"(a) : "l"(p));
    return a;
}
__device__ __forceinline__ void cp_async16(uint32_t dst, const void* src) {
    asm volatile("cp.async.cg.shared.global [%0], [%1], 16;"
                 :: "r"(dst), "l"(src) : "memory");
}
#define CP_COMMIT() asm volatile("cp.async.commit_group;" ::: "memory")
#define CP_WAIT(n)  asm volatile("cp.async.wait_group %0;" :: "n"(n) : "memory")

__device__ __forceinline__ void mma_bf16(float* c, const uint32_t* a, const uint32_t* b) {
    asm volatile(
        "mma.sync.aligned.m16n8k16.row.col.f32.bf16.bf16.f32 "
        "{%0,%1,%2,%3}, {%4,%5,%6,%7}, {%8,%9}, {%0,%1,%2,%3};"
        : "+f"(c[0]), "+f"(c[1]), "+f"(c[2]), "+f"(c[3])
        : "r"(a[0]), "r"(a[1]), "r"(a[2]), "r"(a[3]), "r"(b[0]), "r"(b[1]));
}

// pack two fp32 -> bf16x2 (lo = first element, matching mma b32 layout)
__device__ __forceinline__ uint32_t packbf(float lo, float hi) {
    uint32_t d;
    asm("cvt.rn.bf16x2.f32 %0, %1, %2;" : "=r"(d) : "f"(hi), "f"(lo));
    return d;
}
// residual pair for split precision: r = x - float(bf16(x))
__device__ __forceinline__ uint32_t packbf_res(uint32_t hpack, float lo, float hi) {
    float rl = lo - __uint_as_float(hpack << 16);
    float rh = hi - __uint_as_float(hpack & 0xffff0000u);
    return packbf(rl, rh);
}

// ---------------------------------------------------------------------------
// Conversion kernels
// ---------------------------------------------------------------------------
__global__ __launch_bounds__(256) void conv_split(
    const float4* __restrict__ X, __nv_bfloat162* __restrict__ H,
    __nv_bfloat162* __restrict__ L)
{
    int i = blockIdx.x * 256 + threadIdx.x;
    float4 v = X[i];
    __nv_bfloat16 h0 = __float2bfloat16_rn(v.x), h1 = __float2bfloat16_rn(v.y);
    __nv_bfloat16 h2 = __float2bfloat16_rn(v.z), h3 = __float2bfloat16_rn(v.w);
    __nv_bfloat16 l0 = __float2bfloat16_rn(v.x - __bfloat162float(h0));
    __nv_bfloat16 l1 = __float2bfloat16_rn(v.y - __bfloat162float(h1));
    __nv_bfloat16 l2 = __float2bfloat16_rn(v.z - __bfloat162float(h2));
    __nv_bfloat16 l3 = __float2bfloat16_rn(v.w - __bfloat162float(h3));
    H[2 * i] = __halves2bfloat162(h0, h1); H[2 * i + 1] = __halves2bfloat162(h2, h3);
    L[2 * i] = __halves2bfloat162(l0, l1); L[2 * i + 1] = __halves2bfloat162(l2, l3);
}

__global__ __launch_bounds__(256) void conv_transpose_split(
    const float* __restrict__ B, __nv_bfloat16* __restrict__ H,
    __nv_bfloat16* __restrict__ L, int K, int N)
{
    __shared__ float t[32][33];
    int x = threadIdx.x & 31, y = threadIdx.x >> 5;
    int n0 = blockIdx.x * 32, k0 = blockIdx.y * 32;
#pragma unroll
    for (int j = 0; j < 32; j += 8)
        t[y + j][x] = B[(size_t)(k0 + y + j) * N + n0 + x];
    __syncthreads();
#pragma unroll
    for (int j = 0; j < 32; j += 8) {
        float v = t[x][y + j];
        __nv_bfloat16 h = __float2bfloat16_rn(v);
        __nv_bfloat16 l = __float2bfloat16_rn(v - __bfloat162float(h));
        size_t o = (size_t)(n0 + y + j) * K + k0 + x;
        H[o] = h; L[o] = l;
    }
}

// rotary (first 32 dims) + bf16 hi/lo split of Q and K
__global__ __launch_bounds__(128) void rotconv()
{
    int s = blockIdx.x, h = blockIdx.y, d = threadIdx.x;
    size_t base = ((size_t)h * S_LEN + s) * HS;
    float q = g_Q[base + d], k = g_K[base + d];
    if (d < 32) {
        int j = d & 15;
        float inv  = (float)exp(-(double)j * (9.210340371976184 / 16.0));
        float freq = (float)s * inv;
        float sn, c; sincosf(freq, &sn, &c);
        int pd = (d < 16) ? d + 16 : d - 16;
        float qp = g_Q[base + pd], kp = g_K[base + pd];
        if (d < 16) { q = q * c - qp * sn; k = k * c - kp * sn; }
        else        { q = q * c + qp * sn; k = k * c + kp * sn; }
    }
    __nv_bfloat16 qh = __float2bfloat16_rn(q);
    __nv_bfloat16 kh = __float2bfloat16_rn(k);
    g_Qh[base + d] = qh;
    g_Ql[base + d] = __float2bfloat16_rn(q - __bfloat162float(qh));
    g_Kh[base + d] = kh;
    g_Kl[base + d] = __float2bfloat16_rn(k - __bfloat162float(kh));
}

// V transpose + split: g_V [h][s][d] fp32 -> g_Vth/g_Vtl [h][d][s] bf16
__global__ __launch_bounds__(256) void vtrans()
{
    __shared__ float t[32][33];
    int x = threadIdx.x & 31, y = threadIdx.x >> 5;
    int s0 = blockIdx.x * 32, d0 = blockIdx.y * 32, h = blockIdx.z;
#pragma unroll
    for (int j = 0; j < 32; j += 8)
        t[y + j][x] = g_V[((size_t)h * S_LEN + s0 + y + j) * HS + d0 + x];
    __syncthreads();
#pragma unroll
    for (int j = 0; j < 32; j += 8) {
        float v = t[x][y + j];
        __nv_bfloat16 hv = __float2bfloat16_rn(v);
        size_t o = ((size_t)h * HS + d0 + y + j) * S_LEN + s0 + x;
        g_Vth[o] = hv;
        g_Vtl[o] = __float2bfloat16_rn(v - __bfloat162float(hv));
    }
}

// ---------------------------------------------------------------------------
// bf16x3 mma.sync GEMM, 3-stage cp.async pipeline.
// ---------------------------------------------------------------------------
#define GBK 32
#define GNITER (KTOT / GBK)
#define ROWSTR 40
#define BUFH (128 * ROWSTR)
#define STGH (4 * BUFH)
#define GSTAGES 3
#define GEMM_SMEM (GSTAGES * STGH * 2)   // 122880 bytes

__global__ __launch_bounds__(256, 1) void gemm_mma(
    const __nv_bfloat16* __restrict__ Ah, const __nv_bfloat16* __restrict__ Al,
    const __nv_bfloat16* __restrict__ Bh, const __nv_bfloat16* __restrict__ Bl,
    const float* __restrict__ bias, int N, float* __restrict__ Cout, int mode)
{
    extern __shared__ __align__(16) __nv_bfloat16 sm[];
    const int tid = threadIdx.x;
    const int wid = tid >> 5, lane = tid & 31;
    const int wm = wid >> 2, wn = wid & 3;
    const int n0 = blockIdx.x * 128, m0 = blockIdx.y * 128;
    const uint32_t sbase = smem_to_u32(sm);

    const int r  = lane >> 2;
    const int c2 = (lane & 3) * 2;

    float acc[4][4][4];
#pragma unroll
    for (int i = 0; i < 4; i++)
#pragma unroll
        for (int j = 0; j < 4; j++)
#pragma unroll
            for (int q = 0; q < 4; q++) acc[i][j][q] = 0.f;

    auto load_stage = [&](int s, int k0) {
        const uint32_t st = sbase + (uint32_t)s * STGH * 2;
#pragma unroll
        for (int i = 0; i < 2; i++) {
            int c = tid + i * 256;
            int row = c >> 2, kc = c & 3;
            uint32_t doff = (uint32_t)(row * ROWSTR + kc * 8) * 2;
            size_t goA = (size_t)(m0 + row) * KTOT + k0 + kc * 8;
            size_t goB = (size_t)(n0 + row) * KTOT + k0 + kc * 8;
            cp_async16(st + doff,                Ah + goA);
            cp_async16(st + BUFH * 2 + doff,     Al + goA);
            cp_async16(st + 2 * BUFH * 2 + doff, Bh + goB);
            cp_async16(st + 3 * BUFH * 2 + doff, Bl + goB);
        }
    };

    load_stage(0, 0); CP_COMMIT();
    load_stage(1, GBK); CP_COMMIT();

    for (int it = 0; it < GNITER; it++) {
        const int s = it % GSTAGES;
        if (it < GNITER - 1) { CP_WAIT(1); } else { CP_WAIT(0); }
        __syncthreads();

        const __nv_bfloat16* pAh = sm + s * STGH;
        const __nv_bfloat16* pAl = pAh + BUFH;
        const __nv_bfloat16* pBh = pAh + 2 * BUFH;
        const __nv_bfloat16* pBl = pAh + 3 * BUFH;

#pragma unroll
        for (int ks = 0; ks < 2; ks++) {
            uint32_t ah[4][4], al[4][4], bh[4][2], bl[4][2];
#pragma unroll
            for (int i = 0; i < 4; i++) {
                int ro = (wm * 64 + i * 16 + r) * ROWSTR + ks * 16 + c2;
                ah[i][0] = *reinterpret_cast<const uint32_t*>(pAh + ro);
                ah[i][1] = *reinterpret_cast<const uint32_t*>(pAh + ro + 8 * ROWSTR);
                ah[i][2] = *reinterpret_cast<const uint32_t*>(pAh + ro + 8);
                ah[i][3] = *reinterpret_cast<const uint32_t*>(pAh + ro + 8 * ROWSTR + 8);
                al[i][0] = *reinterpret_cast<const uint32_t*>(pAl + ro);
                al[i][1] = *reinterpret_cast<const uint32_t*>(pAl + ro + 8 * ROWSTR);
                al[i][2] = *reinterpret_cast<const uint32_t*>(pAl + ro + 8);
                al[i][3] = *reinterpret_cast<const uint32_t*>(pAl + ro + 8 * ROWSTR + 8);
            }
#pragma unroll
            for (int j = 0; j < 4; j++) {
                int ro = (wn * 32 + j * 8 + r) * ROWSTR + ks * 16 + c2;
                bh[j][0] = *reinterpret_cast<const uint32_t*>(pBh + ro);
                bh[j][1] = *reinterpret_cast<const uint32_t*>(pBh + ro + 8);
                bl[j][0] = *reinterpret_cast<const uint32_t*>(pBl + ro);
                bl[j][1] = *reinterpret_cast<const uint32_t*>(pBl + ro + 8);
            }
#pragma unroll
            for (int i = 0; i < 4; i++)
#pragma unroll
                for (int j = 0; j < 4; j++) {
                    mma_bf16(acc[i][j], ah[i], bh[j]);
                    mma_bf16(acc[i][j], ah[i], bl[j]);
                    mma_bf16(acc[i][j], al[i], bh[j]);
                }
        }
        if (it + 2 < GNITER) {
            load_stage((it + 2) % GSTAGES, (it + 2) * GBK);
            CP_COMMIT();
        }
    }

#pragma unroll
    for (int i = 0; i < 4; i++) {
#pragma unroll
        for (int j = 0; j < 4; j++) {
            int n = n0 + wn * 32 + j * 8 + c2;
            float2 bv = *reinterpret_cast<const float2*>(bias + n);
#pragma unroll
            for (int half = 0; half < 2; half++) {
                int m = m0 + wm * 64 + i * 16 + r + half * 8;
                float2 v = make_float2(acc[i][j][half * 2] + bv.x,
                                       acc[i][j][half * 2 + 1] + bv.y);
                if (mode) {
                    *reinterpret_cast<float2*>(Cout + (size_t)m * N + n) = v;
                } else {
                    int h = n / 384, e = n - h * 384;
                    int seg = e >> 7, d = e & 127;
                    float* base = (seg == 0) ? g_Q : (seg == 1) ? g_K : g_V;
                    *reinterpret_cast<float2*>(base + ((size_t)h * S_LEN + m) * HS + d) = v;
                }
            }
        }
    }
}

// ---------------------------------------------------------------------------
// Flash attention on mma.sync bf16x3. Block = 128 thr (4 warps), tile 64x64.
// K tile smem stride 136 halves, V^T tile stride 72 halves (conflict-free).
// ---------------------------------------------------------------------------
#define KSTR 136
#define VSTR 72
#define FSM_KH 0
#define FSM_KL (64 * KSTR)
#define FSM_VH (2 * 64 * KSTR)
#define FSM_VL (2 * 64 * KSTR + 128 * VSTR)
#define FLASH_SMEM ((2 * 64 * KSTR + 2 * 128 * VSTR) * 2)   // 71680 bytes

__global__ __launch_bounds__(128) void flash_mma()
{
    const int h  = blockIdx.y;
    const int qt = (gridDim.x - 1) - blockIdx.x;
    const int q0 = qt * 64;

    extern __shared__ __align__(16) __nv_bfloat16 fsm[];
    const uint32_t sbase = smem_to_u32(fsm);

    const int tid = threadIdx.x;
    const int w = tid >> 5, lane = tid & 31;
    const int r = lane >> 2, c2 = (lane & 3) * 2;
    const int qrow = q0 + w * 16 + r;

    const __nv_bfloat16* Qhg = g_Qh + (size_t)h * S_LEN * HS;
    const __nv_bfloat16* Qlg = g_Ql + (size_t)h * S_LEN * HS;
    const __nv_bfloat16* Khg = g_Kh + (size_t)h * S_LEN * HS;
    const __nv_bfloat16* Klg = g_Kl + (size_t)h * S_LEN * HS;
    const __nv_bfloat16* Vhg = g_Vth + (size_t)h * HS * S_LEN;
    const __nv_bfloat16* Vlg = g_Vtl + (size_t)h * HS * S_LEN;

    // preload Q fragments (row-major A, K-major)
    uint32_t qh[8][4], ql[8][4];
#pragma unroll
    for (int kc = 0; kc < 8; kc++) {
        size_t o0 = (size_t)qrow * HS + kc * 16 + c2;
        size_t o1 = (size_t)(qrow + 8) * HS + kc * 16 + c2;
        qh[kc][0] = *reinterpret_cast<const uint32_t*>(Qhg + o0);
        qh[kc][1] = *reinterpret_cast<const uint32_t*>(Qhg + o1);
        qh[kc][2] = *reinterpret_cast<const uint32_t*>(Qhg + o0 + 8);
        qh[kc][3] = *reinterpret_cast<const uint32_t*>(Qhg + o1 + 8);
        ql[kc][0] = *reinterpret_cast<const uint32_t*>(Qlg + o0);
        ql[kc][1] = *reinterpret_cast<const uint32_t*>(Qlg + o1);
        ql[kc][2] = *reinterpret_cast<const uint32_t*>(Qlg + o0 + 8);
        ql[kc][3] = *reinterpret_cast<const uint32_t*>(Qlg + o1 + 8);
    }

    float o[16][4];
#pragma unroll
    for (int t = 0; t < 16; t++)
#pragma unroll
        for (int q = 0; q < 4; q++) o[t][q] = 0.f;
    float m2[2] = {-1e30f, -1e30f};
    float l[2] = {0.f, 0.f};

    const float SC = INV_NORM * 1.4426950408889634f;   // to log2 units

    for (int kt = 0; kt <= qt; kt++) {
        const int kb0 = kt * 64;
        __syncthreads();   // all warps done reading smem from prev iter
        // load K tile (64 x 128) hi/lo and V^T tile (128 x 64) hi/lo
#pragma unroll
        for (int i = 0; i < 8; i++) {
            int c = i * 128 + tid;
            int rowk = c >> 4, colk = c & 15;
            uint32_t dK = (uint32_t)(rowk * KSTR + colk * 8) * 2;
            size_t gK = (size_t)(kb0 + rowk) * HS + colk * 8;
            cp_async16(sbase + FSM_KH * 2 + dK, Khg + gK);
            cp_async16(sbase + FSM_KL * 2 + dK, Klg + gK);
            int rowd = c >> 3, cols = c & 7;
            uint32_t dV = (uint32_t)(rowd * VSTR + cols * 8) * 2;
            size_t gV = (size_t)rowd * S_LEN + kb0 + cols * 8;
            cp_async16(sbase + FSM_VH * 2 + dV, Vhg + gV);
            cp_async16(sbase + FSM_VL * 2 + dV, Vlg + gV);
        }
        CP_COMMIT(); CP_WAIT(0);
        __syncthreads();

        // ---- S = Q K^T ----
        float sacc[8][4];
#pragma unroll
        for (int j = 0; j < 8; j++)
#pragma unroll
            for (int q = 0; q < 4; q++) sacc[j][q] = 0.f;
#pragma unroll
        for (int kc = 0; kc < 8; kc++) {
#pragma unroll
            for (int j = 0; j < 8; j++) {
                int ro = (j * 8 + r) * KSTR + kc * 16 + c2;
                uint32_t bh[2], bl[2];
                bh[0] = *reinterpret_cast<const uint32_t*>(fsm + FSM_KH + ro);
                bh[1] = *reinterpret_cast<const uint32_t*>(fsm + FSM_KH + ro + 8);
                bl[0] = *reinterpret_cast<const uint32_t*>(fsm + FSM_KL + ro);
                bl[1] = *reinterpret_cast<const uint32_t*>(fsm + FSM_KL + ro + 8);
                mma_bf16(sacc[j], qh[kc], bh);
                mma_bf16(sacc[j], qh[kc], bl);
                mma_bf16(sacc[j], ql[kc], bh);
            }
        }

        // ---- causal mask (diagonal tile only) ----
        if (kt == qt) {
#pragma unroll
            for (int j = 0; j < 8; j++) {
#pragma unroll
                for (int q = 0; q < 4; q++) {
                    int col = kb0 + j * 8 + c2 + (q & 1);
                    int row = qrow + ((q >= 2) ? 8 : 0);
                    if (col > row) sacc[j][q] = -1e30f;
                }
            }
        }

        // ---- online softmax (2 row-groups per thread) ----
#pragma unroll
        for (int g = 0; g < 2; g++) {
            float rm = -1e30f;
#pragma unroll
            for (int j = 0; j < 8; j++)
                rm = fmaxf(rm, fmaxf(sacc[j][2 * g], sacc[j][2 * g + 1]));
            rm *= SC;
            rm = fmaxf(rm, __shfl_xor_sync(0xffffffffu, rm, 1));
            rm = fmaxf(rm, __shfl_xor_sync(0xffffffffu, rm, 2));
            float mn = fmaxf(m2[g], rm);
            float alpha = exp2f(m2[g] - mn);
            m2[g] = mn;
            float rs = 0.f;
#pragma unroll
            for (int j = 0; j < 8; j++) {
#pragma unroll
                for (int q = 2 * g; q < 2 * g + 2; q++) {
                    float p = exp2f(sacc[j][q] * SC - mn);
                    sacc[j][q] = p;
                    rs += p;
                }
            }
            rs += __shfl_xor_sync(0xffffffffu, rs, 1);
            rs += __shfl_xor_sync(0xffffffffu, rs, 2);
            l[g] = l[g] * alpha + rs;
#pragma unroll
            for (int t = 0; t < 16; t++) {
                o[t][2 * g]     *= alpha;
                o[t][2 * g + 1] *= alpha;
            }
        }

        // ---- O += P V (P split hi/lo from accumulator regs) ----
#pragma unroll
        for (int kc2 = 0; kc2 < 4; kc2++) {
            uint32_t ph[4], pl[4];
            ph[0] = packbf(sacc[2 * kc2][0], sacc[2 * kc2][1]);
            ph[1] = packbf(sacc[2 * kc2][2], sacc[2 * kc2][3]);
            ph[2] = packbf(sacc[2 * kc2 + 1][0], sacc[2 * kc2 + 1][1]);
            ph[3] = packbf(sacc[2 * kc2 + 1][2], sacc[2 * kc2 + 1][3]);
            pl[0] = packbf_res(ph[0], sacc[2 * kc2][0], sacc[2 * kc2][1]);
            pl[1] = packbf_res(ph[1], sacc[2 * kc2][2], sacc[2 * kc2][3]);
            pl[2] = packbf_res(ph[2], sacc[2 * kc2 + 1][0], sacc[2 * kc2 + 1][1]);
            pl[3] = packbf_res(ph[3], sacc[2 * kc2 + 1][2], sacc[2 * kc2 + 1][3]);
#pragma unroll
            for (int jd = 0; jd < 16; jd++) {
                int ro = (jd * 8 + r) * VSTR + kc2 * 16 + c2;
                uint32_t bh[2], bl[2];
                bh[0] = *reinterpret_cast<const uint32_t*>(fsm + FSM_VH + ro);
                bh[1] = *reinterpret_cast<const uint32_t*>(fsm + FSM_VH + ro + 8);
                bl[0] = *reinterpret_cast<const uint32_t*>(fsm + FSM_VL + ro);
                bl[1] = *reinterpret_cast<const uint32_t*>(fsm + FSM_VL + ro + 8);
                mma_bf16(o[jd], ph, bh);
                mma_bf16(o[jd], ph, bl);
                mma_bf16(o[jd], pl, bh);
            }
        }
    }

    // ---- normalize + store attn output as bf16 hi/lo [s][h*128+d] ----
    float inv0 = 1.f / l[0], inv1 = 1.f / l[1];
#pragma unroll
    for (int jd = 0; jd < 16; jd++) {
        int col = h * HS + jd * 8 + c2;
        {
            float v0 = o[jd][0] * inv0, v1 = o[jd][1] * inv0;
            uint32_t hp = packbf(v0, v1);
            uint32_t lp = packbf_res(hp, v0, v1);
            *reinterpret_cast<uint32_t*>(g_ATh + (size_t)qrow * HID + col) = hp;
            *reinterpret_cast<uint32_t*>(g_ATl + (size_t)qrow * HID + col) = lp;
        }
        {
            float v0 = o[jd][2] * inv1, v1 = o[jd][3] * inv1;
            uint32_t hp = packbf(v0, v1);
            uint32_t lp = packbf_res(hp, v0, v1);
            *reinterpret_cast<uint32_t*>(g_ATh + (size_t)(qrow + 8) * HID + col) = hp;
            *reinterpret_cast<uint32_t*>(g_ATl + (size_t)(qrow + 8) * HID + col) = lp;
        }
    }
}

// ---------------------------------------------------------------------------
extern "C" void kernel_launch(void* const* d_in, const int* in_sizes, int n_in,
                              void* d_out, int out_size)
{
    (void)in_sizes; (void)n_in; (void)out_size;
    const float* hidden = (const float*)d_in[0];
    const float* qkvk = (const float*)d_in[2];
    const float* qkvb = (const float*)d_in[3];
    const float* outk = (const float*)d_in[4];
    const float* outb = (const float*)d_in[5];
    float* out = (float*)d_out;

    cudaFuncSetAttribute(gemm_mma, cudaFuncAttributeMaxDynamicSharedMemorySize, GEMM_SMEM);
    cudaFuncSetAttribute(flash_mma, cudaFuncAttributeMaxDynamicSharedMemorySize, FLASH_SMEM);

    void *Ah, *Al, *Bqh, *Bql, *Boh, *Bol, *ATh, *ATl;
    cudaGetSymbolAddress(&Ah, g_Ah);   cudaGetSymbolAddress(&Al, g_Al);
    cudaGetSymbolAddress(&Bqh, g_Bqh); cudaGetSymbolAddress(&Bql, g_Bql);
    cudaGetSymbolAddress(&Boh, g_Boh); cudaGetSymbolAddress(&Bol, g_Bol);
    cudaGetSymbolAddress(&ATh, g_ATh); cudaGetSymbolAddress(&ATl, g_ATl);

    // 0) operand conversion / transpose
    conv_split<<<(S_LEN * HID) / 1024, 256>>>(
        (const float4*)hidden, (__nv_bfloat162*)Ah, (__nv_bfloat162*)Al);
    conv_transpose_split<<<dim3(QKV_N / 32, HID / 32), 256>>>(
        qkvk, (__nv_bfloat16*)Bqh, (__nv_bfloat16*)Bql, HID, QKV_N);
    conv_transpose_split<<<dim3(HID / 32, HID / 32), 256>>>(
        outk, (__nv_bfloat16*)Boh, (__nv_bfloat16*)Bol, HID, HID);

    // 1) QKV projection + bias, scatter to Q/K/V (fp32)
    gemm_mma<<<dim3(QKV_N / 128, S_LEN / 128), 256, GEMM_SMEM>>>(
        (const __nv_bfloat16*)Ah, (const __nv_bfloat16*)Al,
        (const __nv_bfloat16*)Bqh, (const __nv_bfloat16*)Bql,
        qkvb, QKV_N, nullptr, 0);

    // 2) rotary + bf16 hi/lo split of Q,K ; V transpose + split
    rotconv<<<dim3(S_LEN, NHEADS), 128>>>();
    vtrans<<<dim3(S_LEN / 32, HS / 32, NHEADS), 256>>>();

    // 3) causal flash attention on tensor pipe
    flash_mma<<<dim3(S_LEN / 64, NHEADS), 128, FLASH_SMEM>>>();

    // 4) output projection + bias
    gemm_mma<<<dim3(HID / 128, S_LEN / 128), 256, GEMM_SMEM>>>(
        (const __nv_bfloat16*)ATh, (const __nv_bfloat16*)ATl,
        (const __nv_bfloat16*)Boh, (const __nv_bfloat16*)Bol,
        outb, HID, out, 1);
}

// round 5
// speedup vs baseline: 2.5515x; 1.1161x over previous
#include <cuda_runtime.h>
#include <cuda_bf16.h>
#include <math.h>
#include <stdint.h>

#define S_LEN  2048
#define HID    2048
#define NHEADS 16
#define HS     128
#define QKV_N  6144
#define KTOT   2048
#define INV_NORM 0.08838834764831845f

// ---------------- scratch (device globals; no allocations allowed) ----------
__device__ float g_Q[(size_t)NHEADS * S_LEN * HS];
__device__ float g_K[(size_t)NHEADS * S_LEN * HS];
__device__ float g_V[(size_t)NHEADS * S_LEN * HS];
__device__ __nv_bfloat16 g_Ah[(size_t)S_LEN * HID];
__device__ __nv_bfloat16 g_Al[(size_t)S_LEN * HID];
__device__ __nv_bfloat16 g_Bqh[(size_t)QKV_N * HID];
__device__ __nv_bfloat16 g_Bql[(size_t)QKV_N * HID];
__device__ __nv_bfloat16 g_Boh[(size_t)HID * HID];
__device__ __nv_bfloat16 g_Bol[(size_t)HID * HID];
__device__ __nv_bfloat16 g_ATh[(size_t)S_LEN * HID];
__device__ __nv_bfloat16 g_ATl[(size_t)S_LEN * HID];
__device__ __nv_bfloat16 g_Qh[(size_t)NHEADS * S_LEN * HS];
__device__ __nv_bfloat16 g_Ql[(size_t)NHEADS * S_LEN * HS];
__device__ __nv_bfloat16 g_Kh[(size_t)NHEADS * S_LEN * HS];
__device__ __nv_bfloat16 g_Kl[(size_t)NHEADS * S_LEN * HS];
__device__ __nv_bfloat16 g_Vth[(size_t)NHEADS * HS * S_LEN];
__device__ __nv_bfloat16 g_Vtl[(size_t)NHEADS * HS * S_LEN];

// ------------------------------- helpers ------------------------------------
__device__ __forceinline__ uint32_t smem_to_u32(const void* p) {
    uint32_t a;
    asm("{ .reg .u64 t; cvta.to.shared.u64 t, %1; cvt.u32.u64 %0, t; }"
        : "=r"(a) : "l"(p));
    return a;
}
__device__ __forceinline__ void cp_async16(uint32_t dst, const void* src) {
    asm volatile("cp.async.cg.shared.global [%0], [%1], 16;"
                 :: "r"(dst), "l"(src) : "memory");
}
#define CP_COMMIT() asm volatile("cp.async.commit_group;" ::: "memory")
#define CP_WAIT(n)  asm volatile("cp.async.wait_group %0;" :: "n"(n) : "memory")

__device__ __forceinline__ void mma_bf16(float* c, const uint32_t* a, const uint32_t* b) {
    asm volatile(
        "mma.sync.aligned.m16n8k16.row.col.f32.bf16.bf16.f32 "
        "{%0,%1,%2,%3}, {%4,%5,%6,%7}, {%8,%9}, {%0,%1,%2,%3};"
        : "+f"(c[0]), "+f"(c[1]), "+f"(c[2]), "+f"(c[3])
        : "r"(a[0]), "r"(a[1]), "r"(a[2]), "r"(a[3]), "r"(b[0]), "r"(b[1]));
}
__device__ __forceinline__ void ldsm4(uint32_t& r0, uint32_t& r1, uint32_t& r2,
                                      uint32_t& r3, uint32_t addr) {
    asm volatile("ldmatrix.sync.aligned.m8n8.x4.shared.b16 {%0,%1,%2,%3}, [%4];"
        : "=r"(r0), "=r"(r1), "=r"(r2), "=r"(r3) : "r"(addr));
}
__device__ __forceinline__ uint32_t packbf(float lo, float hi) {
    uint32_t d;
    asm("cvt.rn.bf16x2.f32 %0, %1, %2;" : "=r"(d) : "f"(hi), "f"(lo));
    return d;
}
__device__ __forceinline__ uint32_t packbf_res(uint32_t hpack, float lo, float hi) {
    float rl = lo - __uint_as_float(hpack << 16);
    float rh = hi - __uint_as_float(hpack & 0xffff0000u);
    return packbf(rl, rh);
}

// ---------------------------------------------------------------------------
// Conversion kernels
// ---------------------------------------------------------------------------
__global__ __launch_bounds__(256) void conv_split(
    const float4* __restrict__ X, __nv_bfloat162* __restrict__ H,
    __nv_bfloat162* __restrict__ L)
{
    int i = blockIdx.x * 256 + threadIdx.x;
    float4 v = X[i];
    __nv_bfloat16 h0 = __float2bfloat16_rn(v.x), h1 = __float2bfloat16_rn(v.y);
    __nv_bfloat16 h2 = __float2bfloat16_rn(v.z), h3 = __float2bfloat16_rn(v.w);
    __nv_bfloat16 l0 = __float2bfloat16_rn(v.x - __bfloat162float(h0));
    __nv_bfloat16 l1 = __float2bfloat16_rn(v.y - __bfloat162float(h1));
    __nv_bfloat16 l2 = __float2bfloat16_rn(v.z - __bfloat162float(h2));
    __nv_bfloat16 l3 = __float2bfloat16_rn(v.w - __bfloat162float(h3));
    H[2 * i] = __halves2bfloat162(h0, h1); H[2 * i + 1] = __halves2bfloat162(h2, h3);
    L[2 * i] = __halves2bfloat162(l0, l1); L[2 * i + 1] = __halves2bfloat162(l2, l3);
}

__global__ __launch_bounds__(256) void conv_transpose_split(
    const float* __restrict__ B, __nv_bfloat16* __restrict__ H,
    __nv_bfloat16* __restrict__ L, int K, int N)
{
    __shared__ float t[32][33];
    int x = threadIdx.x & 31, y = threadIdx.x >> 5;
    int n0 = blockIdx.x * 32, k0 = blockIdx.y * 32;
#pragma unroll
    for (int j = 0; j < 32; j += 8)
        t[y + j][x] = B[(size_t)(k0 + y + j) * N + n0 + x];
    __syncthreads();
#pragma unroll
    for (int j = 0; j < 32; j += 8) {
        float v = t[x][y + j];
        __nv_bfloat16 h = __float2bfloat16_rn(v);
        __nv_bfloat16 l = __float2bfloat16_rn(v - __bfloat162float(h));
        size_t o = (size_t)(n0 + y + j) * K + k0 + x;
        H[o] = h; L[o] = l;
    }
}

__global__ __launch_bounds__(128) void rotconv()
{
    int s = blockIdx.x, h = blockIdx.y, d = threadIdx.x;
    size_t base = ((size_t)h * S_LEN + s) * HS;
    float q = g_Q[base + d], k = g_K[base + d];
    if (d < 32) {
        int j = d & 15;
        float inv  = (float)exp(-(double)j * (9.210340371976184 / 16.0));
        float freq = (float)s * inv;
        float sn, c; sincosf(freq, &sn, &c);
        int pd = (d < 16) ? d + 16 : d - 16;
        float qp = g_Q[base + pd], kp = g_K[base + pd];
        if (d < 16) { q = q * c - qp * sn; k = k * c - kp * sn; }
        else        { q = q * c + qp * sn; k = k * c + kp * sn; }
    }
    __nv_bfloat16 qh = __float2bfloat16_rn(q);
    __nv_bfloat16 kh = __float2bfloat16_rn(k);
    g_Qh[base + d] = qh;
    g_Ql[base + d] = __float2bfloat16_rn(q - __bfloat162float(qh));
    g_Kh[base + d] = kh;
    g_Kl[base + d] = __float2bfloat16_rn(k - __bfloat162float(kh));
}

__global__ __launch_bounds__(256) void vtrans()
{
    __shared__ float t[32][33];
    int x = threadIdx.x & 31, y = threadIdx.x >> 5;
    int s0 = blockIdx.x * 32, d0 = blockIdx.y * 32, h = blockIdx.z;
#pragma unroll
    for (int j = 0; j < 32; j += 8)
        t[y + j][x] = g_V[((size_t)h * S_LEN + s0 + y + j) * HS + d0 + x];
    __syncthreads();
#pragma unroll
    for (int j = 0; j < 32; j += 8) {
        float v = t[x][y + j];
        __nv_bfloat16 hv = __float2bfloat16_rn(v);
        size_t o = ((size_t)h * HS + d0 + y + j) * S_LEN + s0 + x;
        g_Vth[o] = hv;
        g_Vtl[o] = __float2bfloat16_rn(v - __bfloat162float(hv));
    }
}

// ---------------------------------------------------------------------------
// bf16x3 mma.sync GEMM, 3-stage cp.async pipeline, ldmatrix fragment loads.
// ---------------------------------------------------------------------------
#define GBK 32
#define GNITER (KTOT / GBK)
#define ROWSTR 40
#define BUFH (128 * ROWSTR)
#define STGH (4 * BUFH)
#define GSTAGES 3
#define GEMM_SMEM (GSTAGES * STGH * 2)

__global__ __launch_bounds__(256, 1) void gemm_mma(
    const __nv_bfloat16* __restrict__ Ah, const __nv_bfloat16* __restrict__ Al,
    const __nv_bfloat16* __restrict__ Bh, const __nv_bfloat16* __restrict__ Bl,
    const float* __restrict__ bias, int N, float* __restrict__ Cout, int mode)
{
    extern __shared__ __align__(16) __nv_bfloat16 sm[];
    const int tid = threadIdx.x;
    const int wid = tid >> 5, lane = tid & 31;
    const int wm = wid >> 2, wn = wid & 3;
    const int n0 = blockIdx.x * 128, m0 = blockIdx.y * 128;
    const uint32_t sbase = smem_to_u32(sm);

    const int r  = lane >> 2;
    const int c2 = (lane & 3) * 2;
    // ldmatrix lane offsets (in halves)
    const int arow = ((lane >> 3) & 1) * 8 + (lane & 7);
    const int acol = (lane >> 4) * 8;
    const int brow = ((lane >> 4) & 1) * 8 + (lane & 7);
    const int bcol = ((lane >> 3) & 1) * 8;

    float acc[4][4][4];
#pragma unroll
    for (int i = 0; i < 4; i++)
#pragma unroll
        for (int j = 0; j < 4; j++)
#pragma unroll
            for (int q = 0; q < 4; q++) acc[i][j][q] = 0.f;

    auto load_stage = [&](int s, int k0) {
        const uint32_t st = sbase + (uint32_t)s * STGH * 2;
#pragma unroll
        for (int i = 0; i < 2; i++) {
            int c = tid + i * 256;
            int row = c >> 2, kc = c & 3;
            uint32_t doff = (uint32_t)(row * ROWSTR + kc * 8) * 2;
            size_t goA = (size_t)(m0 + row) * KTOT + k0 + kc * 8;
            size_t goB = (size_t)(n0 + row) * KTOT + k0 + kc * 8;
            cp_async16(st + doff,                Ah + goA);
            cp_async16(st + BUFH * 2 + doff,     Al + goA);
            cp_async16(st + 2 * BUFH * 2 + doff, Bh + goB);
            cp_async16(st + 3 * BUFH * 2 + doff, Bl + goB);
        }
    };

    load_stage(0, 0); CP_COMMIT();
    load_stage(1, GBK); CP_COMMIT();

    for (int it = 0; it < GNITER; it++) {
        const int s = it % GSTAGES;
        if (it < GNITER - 1) { CP_WAIT(1); } else { CP_WAIT(0); }
        __syncthreads();

        const uint32_t stg = sbase + (uint32_t)s * STGH * 2;

#pragma unroll
        for (int ks = 0; ks < 2; ks++) {
            uint32_t ah[4][4], al[4][4], bh[4][2], bl[4][2];
#pragma unroll
            for (int i = 0; i < 4; i++) {
                uint32_t a = stg + (uint32_t)((wm * 64 + i * 16 + arow) * ROWSTR
                                              + ks * 16 + acol) * 2;
                ldsm4(ah[i][0], ah[i][1], ah[i][2], ah[i][3], a);
                ldsm4(al[i][0], al[i][1], al[i][2], al[i][3], a + BUFH * 2);
            }
#pragma unroll
            for (int jp = 0; jp < 2; jp++) {
                uint32_t b = stg + 2 * BUFH * 2
                           + (uint32_t)((wn * 32 + jp * 16 + brow) * ROWSTR
                                        + ks * 16 + bcol) * 2;
                ldsm4(bh[jp * 2][0], bh[jp * 2][1], bh[jp * 2 + 1][0], bh[jp * 2 + 1][1], b);
                ldsm4(bl[jp * 2][0], bl[jp * 2][1], bl[jp * 2 + 1][0], bl[jp * 2 + 1][1],
                      b + BUFH * 2);
            }
            // three passes -> 16 independent MMA chains each
#pragma unroll
            for (int i = 0; i < 4; i++)
#pragma unroll
                for (int j = 0; j < 4; j++) mma_bf16(acc[i][j], ah[i], bh[j]);
#pragma unroll
            for (int i = 0; i < 4; i++)
#pragma unroll
                for (int j = 0; j < 4; j++) mma_bf16(acc[i][j], ah[i], bl[j]);
#pragma unroll
            for (int i = 0; i < 4; i++)
#pragma unroll
                for (int j = 0; j < 4; j++) mma_bf16(acc[i][j], al[i], bh[j]);
        }
        if (it + 2 < GNITER) {
            load_stage((it + 2) % GSTAGES, (it + 2) * GBK);
            CP_COMMIT();
        }
    }

#pragma unroll
    for (int i = 0; i < 4; i++) {
#pragma unroll
        for (int j = 0; j < 4; j++) {
            int n = n0 + wn * 32 + j * 8 + c2;
            float2 bv = *reinterpret_cast<const float2*>(bias + n);
#pragma unroll
            for (int half = 0; half < 2; half++) {
                int m = m0 + wm * 64 + i * 16 + r + half * 8;
                float2 v = make_float2(acc[i][j][half * 2] + bv.x,
                                       acc[i][j][half * 2 + 1] + bv.y);
                if (mode) {
                    *reinterpret_cast<float2*>(Cout + (size_t)m * N + n) = v;
                } else {
                    int h = n / 384, e = n - h * 384;
                    int seg = e >> 7, d = e & 127;
                    float* base = (seg == 0) ? g_Q : (seg == 1) ? g_K : g_V;
                    *reinterpret_cast<float2*>(base + ((size_t)h * S_LEN + m) * HS + d) = v;
                }
            }
        }
    }
}

// ---------------------------------------------------------------------------
// Flash attention, mma.sync bf16x3 with ldmatrix fragment loads.
// ---------------------------------------------------------------------------
#define KSTR 136
#define VSTR 72
#define FSM_KH 0
#define FSM_KL (64 * KSTR)
#define FSM_VH (2 * 64 * KSTR)
#define FSM_VL (2 * 64 * KSTR + 128 * VSTR)
#define FLASH_SMEM ((2 * 64 * KSTR + 2 * 128 * VSTR) * 2)

__global__ __launch_bounds__(128) void flash_mma()
{
    const int h  = blockIdx.y;
    const int qt = (gridDim.x - 1) - blockIdx.x;
    const int q0 = qt * 64;

    extern __shared__ __align__(16) __nv_bfloat16 fsm[];
    const uint32_t sbase = smem_to_u32(fsm);

    const int tid = threadIdx.x;
    const int w = tid >> 5, lane = tid & 31;
    const int r = lane >> 2, c2 = (lane & 3) * 2;
    const int brow = ((lane >> 4) & 1) * 8 + (lane & 7);
    const int bcol = ((lane >> 3) & 1) * 8;
    const int qrow = q0 + w * 16 + r;

    const __nv_bfloat16* Qhg = g_Qh + (size_t)h * S_LEN * HS;
    const __nv_bfloat16* Qlg = g_Ql + (size_t)h * S_LEN * HS;
    const __nv_bfloat16* Khg = g_Kh + (size_t)h * S_LEN * HS;
    const __nv_bfloat16* Klg = g_Kl + (size_t)h * S_LEN * HS;
    const __nv_bfloat16* Vhg = g_Vth + (size_t)h * HS * S_LEN;
    const __nv_bfloat16* Vlg = g_Vtl + (size_t)h * HS * S_LEN;

    uint32_t qh[8][4], ql[8][4];
#pragma unroll
    for (int kc = 0; kc < 8; kc++) {
        size_t o0 = (size_t)qrow * HS + kc * 16 + c2;
        size_t o1 = (size_t)(qrow + 8) * HS + kc * 16 + c2;
        qh[kc][0] = *reinterpret_cast<const uint32_t*>(Qhg + o0);
        qh[kc][1] = *reinterpret_cast<const uint32_t*>(Qhg + o1);
        qh[kc][2] = *reinterpret_cast<const uint32_t*>(Qhg + o0 + 8);
        qh[kc][3] = *reinterpret_cast<const uint32_t*>(Qhg + o1 + 8);
        ql[kc][0] = *reinterpret_cast<const uint32_t*>(Qlg + o0);
        ql[kc][1] = *reinterpret_cast<const uint32_t*>(Qlg + o1);
        ql[kc][2] = *reinterpret_cast<const uint32_t*>(Qlg + o0 + 8);
        ql[kc][3] = *reinterpret_cast<const uint32_t*>(Qlg + o1 + 8);
    }

    float o[16][4];
#pragma unroll
    for (int t = 0; t < 16; t++)
#pragma unroll
        for (int q = 0; q < 4; q++) o[t][q] = 0.f;
    float m2[2] = {-1e30f, -1e30f};
    float l[2] = {0.f, 0.f};

    const float SC = INV_NORM * 1.4426950408889634f;

    for (int kt = 0; kt <= qt; kt++) {
        const int kb0 = kt * 64;
        __syncthreads();
#pragma unroll
        for (int i = 0; i < 8; i++) {
            int c = i * 128 + tid;
            int rowk = c >> 4, colk = c & 15;
            uint32_t dK = (uint32_t)(rowk * KSTR + colk * 8) * 2;
            size_t gK = (size_t)(kb0 + rowk) * HS + colk * 8;
            cp_async16(sbase + FSM_KH * 2 + dK, Khg + gK);
            cp_async16(sbase + FSM_KL * 2 + dK, Klg + gK);
            int rowd = c >> 3, cols = c & 7;
            uint32_t dV = (uint32_t)(rowd * VSTR + cols * 8) * 2;
            size_t gV = (size_t)rowd * S_LEN + kb0 + cols * 8;
            cp_async16(sbase + FSM_VH * 2 + dV, Vhg + gV);
            cp_async16(sbase + FSM_VL * 2 + dV, Vlg + gV);
        }
        CP_COMMIT(); CP_WAIT(0);
        __syncthreads();

        // ---- S = Q K^T ----
        float sacc[8][4];
#pragma unroll
        for (int j = 0; j < 8; j++)
#pragma unroll
            for (int q = 0; q < 4; q++) sacc[j][q] = 0.f;
#pragma unroll
        for (int kc = 0; kc < 8; kc++) {
#pragma unroll
            for (int jh = 0; jh < 2; jh++) {
                uint32_t bh[4][2], bl[4][2];
#pragma unroll
                for (int jp = 0; jp < 2; jp++) {
                    uint32_t a = sbase
                        + (uint32_t)(((jh * 4 + jp * 2) * 8 + brow) * KSTR
                                     + kc * 16 + bcol) * 2;
                    ldsm4(bh[jp * 2][0], bh[jp * 2][1],
                          bh[jp * 2 + 1][0], bh[jp * 2 + 1][1], a);
                    ldsm4(bl[jp * 2][0], bl[jp * 2][1],
                          bl[jp * 2 + 1][0], bl[jp * 2 + 1][1], a + FSM_KL * 2);
                }
#pragma unroll
                for (int jj = 0; jj < 4; jj++) mma_bf16(sacc[jh * 4 + jj], qh[kc], bh[jj]);
#pragma unroll
                for (int jj = 0; jj < 4; jj++) mma_bf16(sacc[jh * 4 + jj], qh[kc], bl[jj]);
#pragma unroll
                for (int jj = 0; jj < 4; jj++) mma_bf16(sacc[jh * 4 + jj], ql[kc], bh[jj]);
            }
        }

        if (kt == qt) {
#pragma unroll
            for (int j = 0; j < 8; j++) {
#pragma unroll
                for (int q = 0; q < 4; q++) {
                    int col = kb0 + j * 8 + c2 + (q & 1);
                    int row = qrow + ((q >= 2) ? 8 : 0);
                    if (col > row) sacc[j][q] = -1e30f;
                }
            }
        }

#pragma unroll
        for (int g = 0; g < 2; g++) {
            float rm = -1e30f;
#pragma unroll
            for (int j = 0; j < 8; j++)
                rm = fmaxf(rm, fmaxf(sacc[j][2 * g], sacc[j][2 * g + 1]));
            rm *= SC;
            rm = fmaxf(rm, __shfl_xor_sync(0xffffffffu, rm, 1));
            rm = fmaxf(rm, __shfl_xor_sync(0xffffffffu, rm, 2));
            float mn = fmaxf(m2[g], rm);
            float alpha = exp2f(m2[g] - mn);
            m2[g] = mn;
            float rs = 0.f;
#pragma unroll
            for (int j = 0; j < 8; j++) {
#pragma unroll
                for (int q = 2 * g; q < 2 * g + 2; q++) {
                    float p = exp2f(sacc[j][q] * SC - mn);
                    sacc[j][q] = p;
                    rs += p;
                }
            }
            rs += __shfl_xor_sync(0xffffffffu, rs, 1);
            rs += __shfl_xor_sync(0xffffffffu, rs, 2);
            l[g] = l[g] * alpha + rs;
#pragma unroll
            for (int t = 0; t < 16; t++) {
                o[t][2 * g]     *= alpha;
                o[t][2 * g + 1] *= alpha;
            }
        }

        // ---- O += P V ----
#pragma unroll
        for (int kc2 = 0; kc2 < 4; kc2++) {
            uint32_t ph[4], pl[4];
            ph[0] = packbf(sacc[2 * kc2][0], sacc[2 * kc2][1]);
            ph[1] = packbf(sacc[2 * kc2][2], sacc[2 * kc2][3]);
            ph[2] = packbf(sacc[2 * kc2 + 1][0], sacc[2 * kc2 + 1][1]);
            ph[3] = packbf(sacc[2 * kc2 + 1][2], sacc[2 * kc2 + 1][3]);
            pl[0] = packbf_res(ph[0], sacc[2 * kc2][0], sacc[2 * kc2][1]);
            pl[1] = packbf_res(ph[1], sacc[2 * kc2][2], sacc[2 * kc2][3]);
            pl[2] = packbf_res(ph[2], sacc[2 * kc2 + 1][0], sacc[2 * kc2 + 1][1]);
            pl[3] = packbf_res(ph[3], sacc[2 * kc2 + 1][2], sacc[2 * kc2 + 1][3]);
#pragma unroll
            for (int jg = 0; jg < 4; jg++) {
                uint32_t vh[4][2], vl[4][2];
#pragma unroll
                for (int jp = 0; jp < 2; jp++) {
                    uint32_t a = sbase + FSM_VH * 2
                        + (uint32_t)(((jg * 4 + jp * 2) * 8 + brow) * VSTR
                                     + kc2 * 16 + bcol) * 2;
                    ldsm4(vh[jp * 2][0], vh[jp * 2][1],
                          vh[jp * 2 + 1][0], vh[jp * 2 + 1][1], a);
                    ldsm4(vl[jp * 2][0], vl[jp * 2][1],
                          vl[jp * 2 + 1][0], vl[jp * 2 + 1][1],
                          a + (FSM_VL - FSM_VH) * 2);
                }
#pragma unroll
                for (int jj = 0; jj < 4; jj++) mma_bf16(o[jg * 4 + jj], ph, vh[jj]);
#pragma unroll
                for (int jj = 0; jj < 4; jj++) mma_bf16(o[jg * 4 + jj], ph, vl[jj]);
#pragma unroll
                for (int jj = 0; jj < 4; jj++) mma_bf16(o[jg * 4 + jj], pl, vh[jj]);
            }
        }
    }

    float inv0 = 1.f / l[0], inv1 = 1.f / l[1];
#pragma unroll
    for (int jd = 0; jd < 16; jd++) {
        int col = h * HS + jd * 8 + c2;
        {
            float v0 = o[jd][0] * inv0, v1 = o[jd][1] * inv0;
            uint32_t hp = packbf(v0, v1);
            uint32_t lp = packbf_res(hp, v0, v1);
            *reinterpret_cast<uint32_t*>(g_ATh + (size_t)qrow * HID + col) = hp;
            *reinterpret_cast<uint32_t*>(g_ATl + (size_t)qrow * HID + col) = lp;
        }
        {
            float v0 = o[jd][2] * inv1, v1 = o[jd][3] * inv1;
            uint32_t hp = packbf(v0, v1);
            uint32_t lp = packbf_res(hp, v0, v1);
            *reinterpret_cast<uint32_t*>(g_ATh + (size_t)(qrow + 8) * HID + col) = hp;
            *reinterpret_cast<uint32_t*>(g_ATl + (size_t)(qrow + 8) * HID + col) = lp;
        }
    }
}

// ---------------------------------------------------------------------------
extern "C" void kernel_launch(void* const* d_in, const int* in_sizes, int n_in,
                              void* d_out, int out_size)
{
    (void)in_sizes; (void)n_in; (void)out_size;
    const float* hidden = (const float*)d_in[0];
    const float* qkvk = (const float*)d_in[2];
    const float* qkvb = (const float*)d_in[3];
    const float* outk = (const float*)d_in[4];
    const float* outb = (const float*)d_in[5];
    float* out = (float*)d_out;

    cudaFuncSetAttribute(gemm_mma, cudaFuncAttributeMaxDynamicSharedMemorySize, GEMM_SMEM);
    cudaFuncSetAttribute(flash_mma, cudaFuncAttributeMaxDynamicSharedMemorySize, FLASH_SMEM);

    void *Ah, *Al, *Bqh, *Bql, *Boh, *Bol, *ATh, *ATl;
    cudaGetSymbolAddress(&Ah, g_Ah);   cudaGetSymbolAddress(&Al, g_Al);
    cudaGetSymbolAddress(&Bqh, g_Bqh); cudaGetSymbolAddress(&Bql, g_Bql);
    cudaGetSymbolAddress(&Boh, g_Boh); cudaGetSymbolAddress(&Bol, g_Bol);
    cudaGetSymbolAddress(&ATh, g_ATh); cudaGetSymbolAddress(&ATl, g_ATl);

    conv_split<<<(S_LEN * HID) / 1024, 256>>>(
        (const float4*)hidden, (__nv_bfloat162*)Ah, (__nv_bfloat162*)Al);
    conv_transpose_split<<<dim3(QKV_N / 32, HID / 32), 256>>>(
        qkvk, (__nv_bfloat16*)Bqh, (__nv_bfloat16*)Bql, HID, QKV_N);
    conv_transpose_split<<<dim3(HID / 32, HID / 32), 256>>>(
        outk, (__nv_bfloat16*)Boh, (__nv_bfloat16*)Bol, HID, HID);

    gemm_mma<<<dim3(QKV_N / 128, S_LEN / 128), 256, GEMM_SMEM>>>(
        (const __nv_bfloat16*)Ah, (const __nv_bfloat16*)Al,
        (const __nv_bfloat16*)Bqh, (const __nv_bfloat16*)Bql,
        qkvb, QKV_N, nullptr, 0);

    rotconv<<<dim3(S_LEN, NHEADS), 128>>>();
    vtrans<<<dim3(S_LEN / 32, HS / 32, NHEADS), 256>>>();

    flash_mma<<<dim3(S_LEN / 64, NHEADS), 128, FLASH_SMEM>>>();

    gemm_mma<<<dim3(HID / 128, S_LEN / 128), 256, GEMM_SMEM>>>(
        (const __nv_bfloat16*)ATh, (const __nv_bfloat16*)ATl,
        (const __nv_bfloat16*)Boh, (const __nv_bfloat16*)Bol,
        outb, HID, out, 1);
}

// round 6
// speedup vs baseline: 2.8365x; 1.1117x over previous
#include <cuda_runtime.h>
#include <cuda_bf16.h>
#include <math.h>
#include <stdint.h>

#define S_LEN  2048
#define HID    2048
#define NHEADS 16
#define HS     128
#define QKV_N  6144
#define KTOT   2048
#define INV_NORM 0.08838834764831845f

// ---------------- scratch (device globals; no allocations allowed) ----------
__device__ float g_V[(size_t)NHEADS * S_LEN * HS];        // fp32 V [h][s][d]
__device__ __nv_bfloat16 g_Ah[(size_t)S_LEN * HID];
__device__ __nv_bfloat16 g_Al[(size_t)S_LEN * HID];
__device__ __nv_bfloat16 g_Bqh[(size_t)QKV_N * HID];
__device__ __nv_bfloat16 g_Bql[(size_t)QKV_N * HID];
__device__ __nv_bfloat16 g_Boh[(size_t)HID * HID];
__device__ __nv_bfloat16 g_Bol[(size_t)HID * HID];
__device__ __nv_bfloat16 g_ATh[(size_t)S_LEN * HID];
__device__ __nv_bfloat16 g_ATl[(size_t)S_LEN * HID];
__device__ __nv_bfloat16 g_Qh[(size_t)NHEADS * S_LEN * HS];
__device__ __nv_bfloat16 g_Ql[(size_t)NHEADS * S_LEN * HS];
__device__ __nv_bfloat16 g_Kh[(size_t)NHEADS * S_LEN * HS];
__device__ __nv_bfloat16 g_Kl[(size_t)NHEADS * S_LEN * HS];
__device__ __nv_bfloat16 g_Vth[(size_t)NHEADS * HS * S_LEN];
__device__ __nv_bfloat16 g_Vtl[(size_t)NHEADS * HS * S_LEN];

// exact fp32 roundings of 10000^(-j/16) = 10^(-j/4)
__device__ __constant__ float c_invfreq[16] = {
    1.0f, 0.5623413251903491f, 0.31622776601683794f, 0.17782794100389228f,
    0.1f, 0.05623413251903491f, 0.03162277660168379f, 0.017782794100389228f,
    0.01f, 0.005623413251903491f, 0.0031622776601683794f, 0.0017782794100389228f,
    0.001f, 0.0005623413251903491f, 0.00031622776601683794f, 0.00017782794100389228f
};

// ------------------------------- helpers ------------------------------------
__device__ __forceinline__ uint32_t smem_to_u32(const void* p) {
    uint32_t a;
    asm("{ .reg .u64 t; cvta.to.shared.u64 t, %1; cvt.u32.u64 %0, t; }"
        : "=r"(a) : "l"(p));
    return a;
}
__device__ __forceinline__ void cp_async16(uint32_t dst, const void* src) {
    asm volatile("cp.async.cg.shared.global [%0], [%1], 16;"
                 :: "r"(dst), "l"(src) : "memory");
}
#define CP_COMMIT() asm volatile("cp.async.commit_group;" ::: "memory")
#define CP_WAIT(n)  asm volatile("cp.async.wait_group %0;" :: "n"(n) : "memory")

__device__ __forceinline__ void mma_bf16(float* c, const uint32_t* a, const uint32_t* b) {
    asm volatile(
        "mma.sync.aligned.m16n8k16.row.col.f32.bf16.bf16.f32 "
        "{%0,%1,%2,%3}, {%4,%5,%6,%7}, {%8,%9}, {%0,%1,%2,%3};"
        : "+f"(c[0]), "+f"(c[1]), "+f"(c[2]), "+f"(c[3])
        : "r"(a[0]), "r"(a[1]), "r"(a[2]), "r"(a[3]), "r"(b[0]), "r"(b[1]));
}
__device__ __forceinline__ void ldsm4(uint32_t& r0, uint32_t& r1, uint32_t& r2,
                                      uint32_t& r3, uint32_t addr) {
    asm volatile("ldmatrix.sync.aligned.m8n8.x4.shared.b16 {%0,%1,%2,%3}, [%4];"
        : "=r"(r0), "=r"(r1), "=r"(r2), "=r"(r3) : "r"(addr));
}
__device__ __forceinline__ uint32_t packbf(float lo, float hi) {
    uint32_t d;
    asm("cvt.rn.bf16x2.f32 %0, %1, %2;" : "=r"(d) : "f"(hi), "f"(lo));
    return d;
}
__device__ __forceinline__ uint32_t packbf_res(uint32_t hpack, float lo, float hi) {
    float rl = lo - __uint_as_float(hpack << 16);
    float rh = hi - __uint_as_float(hpack & 0xffff0000u);
    return packbf(rl, rh);
}

// ---------------------------------------------------------------------------
// Conversion kernels
// ---------------------------------------------------------------------------
__global__ __launch_bounds__(256) void conv_split(
    const float4* __restrict__ X, __nv_bfloat162* __restrict__ H,
    __nv_bfloat162* __restrict__ L)
{
    int i = blockIdx.x * 256 + threadIdx.x;
    float4 v = X[i];
    __nv_bfloat16 h0 = __float2bfloat16_rn(v.x), h1 = __float2bfloat16_rn(v.y);
    __nv_bfloat16 h2 = __float2bfloat16_rn(v.z), h3 = __float2bfloat16_rn(v.w);
    __nv_bfloat16 l0 = __float2bfloat16_rn(v.x - __bfloat162float(h0));
    __nv_bfloat16 l1 = __float2bfloat16_rn(v.y - __bfloat162float(h1));
    __nv_bfloat16 l2 = __float2bfloat16_rn(v.z - __bfloat162float(h2));
    __nv_bfloat16 l3 = __float2bfloat16_rn(v.w - __bfloat162float(h3));
    H[2 * i] = __halves2bfloat162(h0, h1); H[2 * i + 1] = __halves2bfloat162(h2, h3);
    L[2 * i] = __halves2bfloat162(l0, l1); L[2 * i + 1] = __halves2bfloat162(l2, l3);
}

__global__ __launch_bounds__(256) void conv_transpose_split(
    const float* __restrict__ B, __nv_bfloat16* __restrict__ H,
    __nv_bfloat16* __restrict__ L, int K, int N)
{
    __shared__ float t[32][33];
    int x = threadIdx.x & 31, y = threadIdx.x >> 5;
    int n0 = blockIdx.x * 32, k0 = blockIdx.y * 32;
#pragma unroll
    for (int j = 0; j < 32; j += 8)
        t[y + j][x] = B[(size_t)(k0 + y + j) * N + n0 + x];
    __syncthreads();
#pragma unroll
    for (int j = 0; j < 32; j += 8) {
        float v = t[x][y + j];
        __nv_bfloat16 h = __float2bfloat16_rn(v);
        __nv_bfloat16 l = __float2bfloat16_rn(v - __bfloat162float(h));
        size_t o = (size_t)(n0 + y + j) * K + k0 + x;
        H[o] = h; L[o] = l;
    }
}

__global__ __launch_bounds__(256) void vtrans()
{
    __shared__ float t[32][33];
    int x = threadIdx.x & 31, y = threadIdx.x >> 5;
    int s0 = blockIdx.x * 32, d0 = blockIdx.y * 32, h = blockIdx.z;
#pragma unroll
    for (int j = 0; j < 32; j += 8)
        t[y + j][x] = g_V[((size_t)h * S_LEN + s0 + y + j) * HS + d0 + x];
    __syncthreads();
#pragma unroll
    for (int j = 0; j < 32; j += 8) {
        float v = t[x][y + j];
        __nv_bfloat16 hv = __float2bfloat16_rn(v);
        size_t o = ((size_t)h * HS + d0 + y + j) * S_LEN + s0 + x;
        g_Vth[o] = hv;
        g_Vtl[o] = __float2bfloat16_rn(v - __bfloat162float(hv));
    }
}

// ---------------------------------------------------------------------------
// bf16x3 mma.sync GEMM. BM=64, BN=128, BK=32, 128 threads, 2 CTAs/SM.
// mode 0 epilogue: fused rotary (in-register partner) + Q/K bf16 split,
// V stored fp32 for the vtrans pass.
// ---------------------------------------------------------------------------
#define GBK 32
#define GNITER (KTOT / GBK)
#define ROWSTR 40
#define A_BUFH (64 * ROWSTR)      // 2560 halves
#define B_BUFH (128 * ROWSTR)     // 5120 halves
#define ST_AH 0
#define ST_AL A_BUFH
#define ST_BH (2 * A_BUFH)
#define ST_BL (2 * A_BUFH + B_BUFH)
#define STGH  (2 * A_BUFH + 2 * B_BUFH)   // 15360 halves = 30720 B
#define GSTAGES 3
#define GEMM_SMEM (GSTAGES * STGH * 2)    // 92160 B

__global__ __launch_bounds__(128, 2) void gemm_mma(
    const __nv_bfloat16* __restrict__ Ah, const __nv_bfloat16* __restrict__ Al,
    const __nv_bfloat16* __restrict__ Bh, const __nv_bfloat16* __restrict__ Bl,
    const float* __restrict__ bias, int N, float* __restrict__ Cout, int mode)
{
    extern __shared__ __align__(16) __nv_bfloat16 sm[];
    const int tid = threadIdx.x;
    const int wn = tid >> 5, lane = tid & 31;
    const int n0 = blockIdx.x * 128, m0 = blockIdx.y * 64;
    const uint32_t sbase = smem_to_u32(sm);

    const int r  = lane >> 2;
    const int c2 = (lane & 3) * 2;
    const int arow = ((lane >> 3) & 1) * 8 + (lane & 7);
    const int acol = (lane >> 4) * 8;
    const int brow = ((lane >> 4) & 1) * 8 + (lane & 7);
    const int bcol = ((lane >> 3) & 1) * 8;

    float acc[4][4][4];
#pragma unroll
    for (int i = 0; i < 4; i++)
#pragma unroll
        for (int j = 0; j < 4; j++)
#pragma unroll
            for (int q = 0; q < 4; q++) acc[i][j][q] = 0.f;

    auto load_stage = [&](int s, int k0) {
        const uint32_t st = sbase + (uint32_t)s * STGH * 2;
#pragma unroll
        for (int i = 0; i < 2; i++) {               // A: 256 chunks
            int c = tid + i * 128;
            int row = c >> 2, kc = c & 3;
            uint32_t doff = (uint32_t)(row * ROWSTR + kc * 8) * 2;
            size_t go = (size_t)(m0 + row) * KTOT + k0 + kc * 8;
            cp_async16(st + ST_AH * 2 + doff, Ah + go);
            cp_async16(st + ST_AL * 2 + doff, Al + go);
        }
#pragma unroll
        for (int i = 0; i < 4; i++) {               // B: 512 chunks
            int c = tid + i * 128;
            int row = c >> 2, kc = c & 3;
            uint32_t doff = (uint32_t)(row * ROWSTR + kc * 8) * 2;
            size_t go = (size_t)(n0 + row) * KTOT + k0 + kc * 8;
            cp_async16(st + ST_BH * 2 + doff, Bh + go);
            cp_async16(st + ST_BL * 2 + doff, Bl + go);
        }
    };

    load_stage(0, 0); CP_COMMIT();
    load_stage(1, GBK); CP_COMMIT();

    for (int it = 0; it < GNITER; it++) {
        const int s = it % GSTAGES;
        if (it < GNITER - 1) { CP_WAIT(1); } else { CP_WAIT(0); }
        __syncthreads();

        const uint32_t stg = sbase + (uint32_t)s * STGH * 2;

#pragma unroll
        for (int ks = 0; ks < 2; ks++) {
            uint32_t ah[4][4], al[4][4], bh[4][2], bl[4][2];
#pragma unroll
            for (int i = 0; i < 4; i++) {
                uint32_t a = stg + (uint32_t)((i * 16 + arow) * ROWSTR
                                              + ks * 16 + acol) * 2;
                ldsm4(ah[i][0], ah[i][1], ah[i][2], ah[i][3], a + ST_AH * 2);
                ldsm4(al[i][0], al[i][1], al[i][2], al[i][3], a + ST_AL * 2);
            }
#pragma unroll
            for (int jp = 0; jp < 2; jp++) {
                uint32_t b = stg + (uint32_t)((wn * 32 + jp * 16 + brow) * ROWSTR
                                              + ks * 16 + bcol) * 2;
                ldsm4(bh[jp * 2][0], bh[jp * 2][1], bh[jp * 2 + 1][0], bh[jp * 2 + 1][1],
                      b + ST_BH * 2);
                ldsm4(bl[jp * 2][0], bl[jp * 2][1], bl[jp * 2 + 1][0], bl[jp * 2 + 1][1],
                      b + ST_BL * 2);
            }
#pragma unroll
            for (int i = 0; i < 4; i++)
#pragma unroll
                for (int j = 0; j < 4; j++) mma_bf16(acc[i][j], ah[i], bh[j]);
#pragma unroll
            for (int i = 0; i < 4; i++)
#pragma unroll
                for (int j = 0; j < 4; j++) mma_bf16(acc[i][j], ah[i], bl[j]);
#pragma unroll
            for (int i = 0; i < 4; i++)
#pragma unroll
                for (int j = 0; j < 4; j++) mma_bf16(acc[i][j], al[i], bh[j]);
        }
        if (it + 2 < GNITER) {
            load_stage((it + 2) % GSTAGES, (it + 2) * GBK);
            CP_COMMIT();
        }
    }

#pragma unroll
    for (int i = 0; i < 4; i++) {
#pragma unroll
        for (int j = 0; j < 4; j++) {
            int n = n0 + wn * 32 + j * 8 + c2;
            float2 bv = *reinterpret_cast<const float2*>(bias + n);
#pragma unroll
            for (int half = 0; half < 2; half++) {
                int m = m0 + i * 16 + r + half * 8;
                float2 v = make_float2(acc[i][j][half * 2] + bv.x,
                                       acc[i][j][half * 2 + 1] + bv.y);
                if (mode) {
                    *reinterpret_cast<float2*>(Cout + (size_t)m * N + n) = v;
                } else {
                    int h = n / 384, e = n - h * 384;
                    int seg = e >> 7, d = e & 127;
                    if (seg == 2) {
                        *reinterpret_cast<float2*>(g_V + ((size_t)h * S_LEN + m) * HS + d) = v;
                    } else {
                        if (d < 32) {   // fused rotary: partner is acc[i][j±2]
                            bool low = d < 16;
                            int jp = low ? j + 2 : j - 2;
                            int np = low ? n + 16 : n - 16;
                            float2 bvp = *reinterpret_cast<const float2*>(bias + np);
                            float px = acc[i][jp][half * 2] + bvp.x;
                            float py = acc[i][jp][half * 2 + 1] + bvp.y;
                            float f0 = (float)m * c_invfreq[d & 15];
                            float f1 = (float)m * c_invfreq[(d + 1) & 15];
                            float s0, c0, s1, c1;
                            sincosf(f0, &s0, &c0);
                            sincosf(f1, &s1, &c1);
                            if (low) { v.x = v.x * c0 - px * s0; v.y = v.y * c1 - py * s1; }
                            else     { v.x = v.x * c0 + px * s0; v.y = v.y * c1 + py * s1; }
                        }
                        uint32_t hp = packbf(v.x, v.y);
                        uint32_t lp = packbf_res(hp, v.x, v.y);
                        size_t off = ((size_t)h * S_LEN + m) * HS + d;
                        if (seg == 0) {
                            *reinterpret_cast<uint32_t*>(g_Qh + off) = hp;
                            *reinterpret_cast<uint32_t*>(g_Ql + off) = lp;
                        } else {
                            *reinterpret_cast<uint32_t*>(g_Kh + off) = hp;
                            *reinterpret_cast<uint32_t*>(g_Kl + off) = lp;
                        }
                    }
                }
            }
        }
    }
}

// ---------------------------------------------------------------------------
// Flash attention, mma.sync bf16x3 with ldmatrix fragment loads.
// ---------------------------------------------------------------------------
#define KSTR 136
#define VSTR 72
#define FSM_KH 0
#define FSM_KL (64 * KSTR)
#define FSM_VH (2 * 64 * KSTR)
#define FSM_VL (2 * 64 * KSTR + 128 * VSTR)
#define FLASH_SMEM ((2 * 64 * KSTR + 2 * 128 * VSTR) * 2)

__global__ __launch_bounds__(128) void flash_mma()
{
    const int h  = blockIdx.y;
    const int qt = (gridDim.x - 1) - blockIdx.x;
    const int q0 = qt * 64;

    extern __shared__ __align__(16) __nv_bfloat16 fsm[];
    const uint32_t sbase = smem_to_u32(fsm);

    const int tid = threadIdx.x;
    const int w = tid >> 5, lane = tid & 31;
    const int r = lane >> 2, c2 = (lane & 3) * 2;
    const int brow = ((lane >> 4) & 1) * 8 + (lane & 7);
    const int bcol = ((lane >> 3) & 1) * 8;
    const int qrow = q0 + w * 16 + r;

    const __nv_bfloat16* Qhg = g_Qh + (size_t)h * S_LEN * HS;
    const __nv_bfloat16* Qlg = g_Ql + (size_t)h * S_LEN * HS;
    const __nv_bfloat16* Khg = g_Kh + (size_t)h * S_LEN * HS;
    const __nv_bfloat16* Klg = g_Kl + (size_t)h * S_LEN * HS;
    const __nv_bfloat16* Vhg = g_Vth + (size_t)h * HS * S_LEN;
    const __nv_bfloat16* Vlg = g_Vtl + (size_t)h * HS * S_LEN;

    uint32_t qh[8][4], ql[8][4];
#pragma unroll
    for (int kc = 0; kc < 8; kc++) {
        size_t o0 = (size_t)qrow * HS + kc * 16 + c2;
        size_t o1 = (size_t)(qrow + 8) * HS + kc * 16 + c2;
        qh[kc][0] = *reinterpret_cast<const uint32_t*>(Qhg + o0);
        qh[kc][1] = *reinterpret_cast<const uint32_t*>(Qhg + o1);
        qh[kc][2] = *reinterpret_cast<const uint32_t*>(Qhg + o0 + 8);
        qh[kc][3] = *reinterpret_cast<const uint32_t*>(Qhg + o1 + 8);
        ql[kc][0] = *reinterpret_cast<const uint32_t*>(Qlg + o0);
        ql[kc][1] = *reinterpret_cast<const uint32_t*>(Qlg + o1);
        ql[kc][2] = *reinterpret_cast<const uint32_t*>(Qlg + o0 + 8);
        ql[kc][3] = *reinterpret_cast<const uint32_t*>(Qlg + o1 + 8);
    }

    float o[16][4];
#pragma unroll
    for (int t = 0; t < 16; t++)
#pragma unroll
        for (int q = 0; q < 4; q++) o[t][q] = 0.f;
    float m2[2] = {-1e30f, -1e30f};
    float l[2] = {0.f, 0.f};

    const float SC = INV_NORM * 1.4426950408889634f;

    for (int kt = 0; kt <= qt; kt++) {
        const int kb0 = kt * 64;
        __syncthreads();
#pragma unroll
        for (int i = 0; i < 8; i++) {
            int c = i * 128 + tid;
            int rowk = c >> 4, colk = c & 15;
            uint32_t dK = (uint32_t)(rowk * KSTR + colk * 8) * 2;
            size_t gK = (size_t)(kb0 + rowk) * HS + colk * 8;
            cp_async16(sbase + FSM_KH * 2 + dK, Khg + gK);
            cp_async16(sbase + FSM_KL * 2 + dK, Klg + gK);
            int rowd = c >> 3, cols = c & 7;
            uint32_t dV = (uint32_t)(rowd * VSTR + cols * 8) * 2;
            size_t gV = (size_t)rowd * S_LEN + kb0 + cols * 8;
            cp_async16(sbase + FSM_VH * 2 + dV, Vhg + gV);
            cp_async16(sbase + FSM_VL * 2 + dV, Vlg + gV);
        }
        CP_COMMIT(); CP_WAIT(0);
        __syncthreads();

        float sacc[8][4];
#pragma unroll
        for (int j = 0; j < 8; j++)
#pragma unroll
            for (int q = 0; q < 4; q++) sacc[j][q] = 0.f;
#pragma unroll
        for (int kc = 0; kc < 8; kc++) {
#pragma unroll
            for (int jh = 0; jh < 2; jh++) {
                uint32_t bh[4][2], bl[4][2];
#pragma unroll
                for (int jp = 0; jp < 2; jp++) {
                    uint32_t a = sbase
                        + (uint32_t)(((jh * 4 + jp * 2) * 8 + brow) * KSTR
                                     + kc * 16 + bcol) * 2;
                    ldsm4(bh[jp * 2][0], bh[jp * 2][1],
                          bh[jp * 2 + 1][0], bh[jp * 2 + 1][1], a);
                    ldsm4(bl[jp * 2][0], bl[jp * 2][1],
                          bl[jp * 2 + 1][0], bl[jp * 2 + 1][1], a + FSM_KL * 2);
                }
#pragma unroll
                for (int jj = 0; jj < 4; jj++) mma_bf16(sacc[jh * 4 + jj], qh[kc], bh[jj]);
#pragma unroll
                for (int jj = 0; jj < 4; jj++) mma_bf16(sacc[jh * 4 + jj], qh[kc], bl[jj]);
#pragma unroll
                for (int jj = 0; jj < 4; jj++) mma_bf16(sacc[jh * 4 + jj], ql[kc], bh[jj]);
            }
        }

        if (kt == qt) {
#pragma unroll
            for (int j = 0; j < 8; j++) {
#pragma unroll
                for (int q = 0; q < 4; q++) {
                    int col = kb0 + j * 8 + c2 + (q & 1);
                    int row = qrow + ((q >= 2) ? 8 : 0);
                    if (col > row) sacc[j][q] = -1e30f;
                }
            }
        }

#pragma unroll
        for (int g = 0; g < 2; g++) {
            float rm = -1e30f;
#pragma unroll
            for (int j = 0; j < 8; j++)
                rm = fmaxf(rm, fmaxf(sacc[j][2 * g], sacc[j][2 * g + 1]));
            rm *= SC;
            rm = fmaxf(rm, __shfl_xor_sync(0xffffffffu, rm, 1));
            rm = fmaxf(rm, __shfl_xor_sync(0xffffffffu, rm, 2));
            float mn = fmaxf(m2[g], rm);
            float alpha = exp2f(m2[g] - mn);
            m2[g] = mn;
            float rs = 0.f;
#pragma unroll
            for (int j = 0; j < 8; j++) {
#pragma unroll
                for (int q = 2 * g; q < 2 * g + 2; q++) {
                    float p = exp2f(sacc[j][q] * SC - mn);
                    sacc[j][q] = p;
                    rs += p;
                }
            }
            rs += __shfl_xor_sync(0xffffffffu, rs, 1);
            rs += __shfl_xor_sync(0xffffffffu, rs, 2);
            l[g] = l[g] * alpha + rs;
#pragma unroll
            for (int t = 0; t < 16; t++) {
                o[t][2 * g]     *= alpha;
                o[t][2 * g + 1] *= alpha;
            }
        }

#pragma unroll
        for (int kc2 = 0; kc2 < 4; kc2++) {
            uint32_t ph[4], pl[4];
            ph[0] = packbf(sacc[2 * kc2][0], sacc[2 * kc2][1]);
            ph[1] = packbf(sacc[2 * kc2][2], sacc[2 * kc2][3]);
            ph[2] = packbf(sacc[2 * kc2 + 1][0], sacc[2 * kc2 + 1][1]);
            ph[3] = packbf(sacc[2 * kc2 + 1][2], sacc[2 * kc2 + 1][3]);
            pl[0] = packbf_res(ph[0], sacc[2 * kc2][0], sacc[2 * kc2][1]);
            pl[1] = packbf_res(ph[1], sacc[2 * kc2][2], sacc[2 * kc2][3]);
            pl[2] = packbf_res(ph[2], sacc[2 * kc2 + 1][0], sacc[2 * kc2 + 1][1]);
            pl[3] = packbf_res(ph[3], sacc[2 * kc2 + 1][2], sacc[2 * kc2 + 1][3]);
#pragma unroll
            for (int jg = 0; jg < 4; jg++) {
                uint32_t vh[4][2], vl[4][2];
#pragma unroll
                for (int jp = 0; jp < 2; jp++) {
                    uint32_t a = sbase + FSM_VH * 2
                        + (uint32_t)(((jg * 4 + jp * 2) * 8 + brow) * VSTR
                                     + kc2 * 16 + bcol) * 2;
                    ldsm4(vh[jp * 2][0], vh[jp * 2][1],
                          vh[jp * 2 + 1][0], vh[jp * 2 + 1][1], a);
                    ldsm4(vl[jp * 2][0], vl[jp * 2][1],
                          vl[jp * 2 + 1][0], vl[jp * 2 + 1][1],
                          a + (FSM_VL - FSM_VH) * 2);
                }
#pragma unroll
                for (int jj = 0; jj < 4; jj++) mma_bf16(o[jg * 4 + jj], ph, vh[jj]);
#pragma unroll
                for (int jj = 0; jj < 4; jj++) mma_bf16(o[jg * 4 + jj], ph, vl[jj]);
#pragma unroll
                for (int jj = 0; jj < 4; jj++) mma_bf16(o[jg * 4 + jj], pl, vh[jj]);
            }
        }
    }

    float inv0 = 1.f / l[0], inv1 = 1.f / l[1];
#pragma unroll
    for (int jd = 0; jd < 16; jd++) {
        int col = h * HS + jd * 8 + c2;
        {
            float v0 = o[jd][0] * inv0, v1 = o[jd][1] * inv0;
            uint32_t hp = packbf(v0, v1);
            uint32_t lp = packbf_res(hp, v0, v1);
            *reinterpret_cast<uint32_t*>(g_ATh + (size_t)qrow * HID + col) = hp;
            *reinterpret_cast<uint32_t*>(g_ATl + (size_t)qrow * HID + col) = lp;
        }
        {
            float v0 = o[jd][2] * inv1, v1 = o[jd][3] * inv1;
            uint32_t hp = packbf(v0, v1);
            uint32_t lp = packbf_res(hp, v0, v1);
            *reinterpret_cast<uint32_t*>(g_ATh + (size_t)(qrow + 8) * HID + col) = hp;
            *reinterpret_cast<uint32_t*>(g_ATl + (size_t)(qrow + 8) * HID + col) = lp;
        }
    }
}

// ---------------------------------------------------------------------------
extern "C" void kernel_launch(void* const* d_in, const int* in_sizes, int n_in,
                              void* d_out, int out_size)
{
    (void)in_sizes; (void)n_in; (void)out_size;
    const float* hidden = (const float*)d_in[0];
    const float* qkvk = (const float*)d_in[2];
    const float* qkvb = (const float*)d_in[3];
    const float* outk = (const float*)d_in[4];
    const float* outb = (const float*)d_in[5];
    float* out = (float*)d_out;

    cudaFuncSetAttribute(gemm_mma, cudaFuncAttributeMaxDynamicSharedMemorySize, GEMM_SMEM);
    cudaFuncSetAttribute(flash_mma, cudaFuncAttributeMaxDynamicSharedMemorySize, FLASH_SMEM);

    void *Ah, *Al, *Bqh, *Bql, *Boh, *Bol, *ATh, *ATl;
    cudaGetSymbolAddress(&Ah, g_Ah);   cudaGetSymbolAddress(&Al, g_Al);
    cudaGetSymbolAddress(&Bqh, g_Bqh); cudaGetSymbolAddress(&Bql, g_Bql);
    cudaGetSymbolAddress(&Boh, g_Boh); cudaGetSymbolAddress(&Bol, g_Bol);
    cudaGetSymbolAddress(&ATh, g_ATh); cudaGetSymbolAddress(&ATl, g_ATl);

    conv_split<<<(S_LEN * HID) / 1024, 256>>>(
        (const float4*)hidden, (__nv_bfloat162*)Ah, (__nv_bfloat162*)Al);
    conv_transpose_split<<<dim3(QKV_N / 32, HID / 32), 256>>>(
        qkvk, (__nv_bfloat16*)Bqh, (__nv_bfloat16*)Bql, HID, QKV_N);
    conv_transpose_split<<<dim3(HID / 32, HID / 32), 256>>>(
        outk, (__nv_bfloat16*)Boh, (__nv_bfloat16*)Bol, HID, HID);

    // QKV projection + fused rotary + Q/K split (V -> fp32)
    gemm_mma<<<dim3(QKV_N / 128, S_LEN / 64), 128, GEMM_SMEM>>>(
        (const __nv_bfloat16*)Ah, (const __nv_bfloat16*)Al,
        (const __nv_bfloat16*)Bqh, (const __nv_bfloat16*)Bql,
        qkvb, QKV_N, nullptr, 0);

    vtrans<<<dim3(S_LEN / 32, HS / 32, NHEADS), 256>>>();

    flash_mma<<<dim3(S_LEN / 64, NHEADS), 128, FLASH_SMEM>>>();

    gemm_mma<<<dim3(HID / 128, S_LEN / 64), 128, GEMM_SMEM>>>(
        (const __nv_bfloat16*)ATh, (const __nv_bfloat16*)ATl,
        (const __nv_bfloat16*)Boh, (const __nv_bfloat16*)Bol,
        outb, HID, out, 1);
}